// round 11
// baseline (speedup 1.0000x reference)
#include <cuda_runtime.h>
#include <cuda_bf16.h>
#include <cstdint>

// Problem constants (fixed for this dataset)
#define B_   64
#define D_   256
#define HW_  1024            // 32*32
#define K_   1024            // num embeddings
#define NPIX (B_ * HW_)      // 65536
#define NELM (B_ * D_ * HW_) // 16777216
#define CAND_CAP 1048576
#define EPS_MARGIN 5e-3f
#define STAGE_CAP 2816
#define MULTI_CAP 1024

// ---------------------------------------------------------------------------
// Scratch (device globals; no cudaMalloc allowed)
// ---------------------------------------------------------------------------
__device__ unsigned long long g_best[NPIX];   // packed (orderable_score<<32)|k
__device__ float g_cn[K_];                    // |c_k|^2 (exact sequential chain)
__device__ float g_A[NPIX];                   // |x_n|^2 (exact sequential chain)
__device__ float g_Xt[NPIX * D_];             // X transposed: [pix][d] fp32
__device__ __nv_bfloat16 g_Xt_bf[NPIX * D_];  // bf16 copy
__device__ __nv_bfloat16 g_Cbf[K_ * D_];      // codebook bf16
__device__ unsigned long long g_cand[CAND_CAP]; // overflow-only fallback
__device__ unsigned int g_ncand;

__device__ __forceinline__ unsigned int float_to_ordered(float f) {
    unsigned int u = __float_as_uint(f);
    return (u & 0x80000000u) ? ~u : (u | 0x80000000u);
}
__device__ __forceinline__ float ordered_to_float(unsigned int o) {
    unsigned int u = (o & 0x80000000u) ? (o & 0x7FFFFFFFu) : ~o;
    return __uint_as_float(u);
}

__device__ __forceinline__ uint32_t smem_u32(const void* p) {
    uint32_t a;
    asm("{ .reg .u64 t; cvta.to.shared.u64 t, %1; cvt.u32.u64 %0, t; }"
        : "=r"(a) : "l"(p));
    return a;
}

// cp.async 16B (sm_80+, legal on plain sm_103 target)
__device__ __forceinline__ void cp16(uint32_t saddr, const void* g) {
    asm volatile("cp.async.cg.shared.global [%0], [%1], 16;"
                 :: "r"(saddr), "l"(g) : "memory");
}

// ldmatrix x4 (non-transposed, b16)
__device__ __forceinline__ void ldm_x4(uint32_t* r, uint32_t addr) {
    asm volatile("ldmatrix.sync.aligned.m8n8.x4.shared.b16 {%0,%1,%2,%3}, [%4];"
                 : "=r"(r[0]), "=r"(r[1]), "=r"(r[2]), "=r"(r[3]) : "r"(addr));
}

// bf16 HMMA m16n8k16, f32 accumulate (sm_80+)
__device__ __forceinline__ void mma_bf16(float* c, const uint32_t* a,
                                         uint32_t b0, uint32_t b1) {
    asm volatile(
        "mma.sync.aligned.m16n8k16.row.col.f32.bf16.bf16.f32 "
        "{%0,%1,%2,%3}, {%4,%5,%6,%7}, {%8,%9}, {%0,%1,%2,%3};"
        : "+f"(c[0]), "+f"(c[1]), "+f"(c[2]), "+f"(c[3])
        : "r"(a[0]), "r"(a[1]), "r"(a[2]), "r"(a[3]), "r"(b0), "r"(b1));
}

// ---------------------------------------------------------------------------
// Kernel 1 (FUSED prologue): one grid, three independent roles overlapped.
//   blocks [0, 16384)      : transpose X NCHW -> pixel-major f32+bf16
//   blocks [16384, 16640)  : |x_p|^2 exact sequential chain
//   blocks [16640, 16672)  : |c_k|^2 exact chain + codebook bf16 convert
// ---------------------------------------------------------------------------
__global__ __launch_bounds__(256)
void prologue_kernel(const float* __restrict__ X, const float* __restrict__ C) {
    __shared__ float sm[32][257];   // cn rows; transpose uses a 32x33 corner
    const int bid = blockIdx.x;
    const int tid = threadIdx.x;

    if (bid < 16384) {
        // ---- transpose: block covers (b, dB..dB+31, pB..pB+31) ----
        const int b  = bid >> 8;
        const int r8 = bid & 255;
        const int dB = (r8 >> 5) * 32;
        const int pB = (r8 & 31) * 32;
        const int tx = tid & 31;
        const int ty = tid >> 5;   // 0..7

        const float* src = X + ((size_t)b * D_ + dB) * HW_ + pB;
        #pragma unroll
        for (int i = 0; i < 32; i += 8)
            sm[ty + i][tx] = src[(size_t)(ty + i) * HW_ + tx];
        __syncthreads();

        const size_t obase = ((size_t)(b * HW_ + pB)) * D_ + dB;
        #pragma unroll
        for (int i = 0; i < 32; i += 8) {
            int row = ty + i;
            float v = sm[tx][row];
            g_Xt[obase + (size_t)row * D_ + tx] = v;
            g_Xt_bf[obase + (size_t)row * D_ + tx] = __float2bfloat16(v);
        }
    } else if (bid < 16640) {
        // ---- |x|^2: exact sequential chain, coalesced strided loads ----
        const int pix = (bid - 16384) * 256 + tid;
        const int b = pix >> 10, p = pix & 1023;
        const float* Xb = X + (size_t)b * D_ * HW_ + p;
        float s = 0.f;
        #pragma unroll 8
        for (int d = 0; d < D_; d++) {
            float v = Xb[(size_t)d * HW_];
            s = __fadd_rn(s, __fmul_rn(v, v));
        }
        g_A[pix] = s;
    } else {
        // ---- |c|^2 + bf16 convert, smem-staged coalesced ----
        const int kb = (bid - 16640) * 32;
        if (bid == 16640 && tid == 0) g_ncand = 0;

        const float4* C4 = reinterpret_cast<const float4*>(C + (size_t)kb * D_);
        uint2* B2 = reinterpret_cast<uint2*>(g_Cbf + (size_t)kb * D_);
        #pragma unroll
        for (int i = 0; i < 8; i++) {
            int idx = i * 256 + tid;          // float4 index: 0..2047
            int r = idx >> 6, c = idx & 63;
            float4 v = C4[idx];
            sm[r][c * 4 + 0] = v.x;
            sm[r][c * 4 + 1] = v.y;
            sm[r][c * 4 + 2] = v.z;
            sm[r][c * 4 + 3] = v.w;
            __nv_bfloat162 h01 = __floats2bfloat162_rn(v.x, v.y);
            __nv_bfloat162 h23 = __floats2bfloat162_rn(v.z, v.w);
            uint2 pk;
            pk.x = *reinterpret_cast<unsigned int*>(&h01);
            pk.y = *reinterpret_cast<unsigned int*>(&h23);
            B2[idx] = pk;
        }
        __syncthreads();
        if (tid < 32) {
            float s = 0.f;
            #pragma unroll 8
            for (int d = 0; d < D_; d++) {
                float v = sm[tid][d];
                s = __fadd_rn(s, __fmul_rn(v, v));
            }
            g_cn[kb + tid] = s;
        }
    }
}

// ---------------------------------------------------------------------------
// Kernel 2: persistent-A bf16 HMMA GEMM, 128 pixels x ALL 1024 codes per CTA.
// 512 threads / 16 warps, 32x32 warp tile, 2-stage register fragment pipeline.
// Ballot-aggregated candidate staging; singles write g_best directly with full
// score A + (cn - 2dot); multis are exactly rescored IN-CTA (g_Xt rows are
// coalesced 1KB reads, C rows L2-hot) with the Round-2-validated chain.
// Overflow (statistically never) falls back to g_cand + rescore_kernel.
// ---------------------------------------------------------------------------
__global__ __launch_bounds__(512, 1)
void vq_mma_kernel(const float* __restrict__ C) {
    extern __shared__ char dsm_raw[];
    __shared__ float s_cn[K_];
    __shared__ float s_A[128];
    __shared__ unsigned int s_min[128];
    __shared__ unsigned int s_pcount[128];
    __shared__ unsigned long long stage[STAGE_CAP];
    __shared__ unsigned int s_multi[MULTI_CAP];
    __shared__ unsigned int s_cnt, s_mcnt;

    const int tid = threadIdx.x, lane = tid & 31, wid = tid >> 5;
    const int pt = blockIdx.x;   // 0..511 pixel tiles (128 pixels each)

    const uint32_t s0 = smem_u32(dsm_raw);
    const uint32_t base = (s0 + 1023) & ~1023u;
    const uint32_t sA = base;
    const uint32_t sB0 = base + 65536, sB1 = base + 131072;

    #pragma unroll
    for (int i = 0; i < 2; i++) s_cn[tid + i * 512] = g_cn[tid + i * 512];
    if (tid < 128) {
        s_min[tid] = 0xFFFFFFFFu;
        s_pcount[tid] = 0u;
        s_A[tid] = g_A[pt * 128 + tid];
        g_best[pt * 128 + tid] = 0xFFFFFFFFFFFFFFFFull;
    }
    if (tid == 0) { s_cnt = 0; s_mcnt = 0; }

    // Stage A (once) + B tile 0
    const __nv_bfloat16* gA = g_Xt_bf + (size_t)pt * 128 * D_;
    #pragma unroll
    for (int i = 0; i < 8; i++) {
        int v = i * 512 + tid;             // 0..4095 16B chunks
        int r = v >> 5, c = v & 31;
        uint32_t off = (uint32_t)(r * 512) + (((uint32_t)c * 16) ^ ((uint32_t)(r & 7) << 4));
        cp16(sA + off, gA + (size_t)v * 8);
        cp16(sB0 + off, g_Cbf + (size_t)v * 8);
    }
    asm volatile("cp.async.commit_group;");

    // Warp tiling: 4 (m) x 4 (n), 32x32 per warp
    const int wm = (wid & 3) * 32;
    const int wn = (wid >> 2) * 32;
    const int a_row = wm + (lane & 15);
    const uint32_t a_swz = (uint32_t)((a_row & 7) << 4);
    const int a_kb = (lane >> 4) * 16;
    const int b_row = wn + ((lane & 7) | ((lane & 16) >> 1));
    const uint32_t b_swz = (uint32_t)((b_row & 7) << 4);
    const int b_kb = ((lane >> 3) & 1) * 16;

    const int r0b = wm + (lane >> 2);          // score row base (mi adds 16)
    const int c0b = wn + (lane & 3) * 2;       // score col base (nt adds 8)

    const uint32_t aAddr0 = sA + (uint32_t)a_row * 512;
    const uint32_t aAddr1 = sA + (uint32_t)(a_row + 16) * 512;

    for (int kt = 0; kt < 8; kt++) {
        const uint32_t sBc = (kt & 1) ? sB1 : sB0;
        const uint32_t sBn = (kt & 1) ? sB0 : sB1;

        asm volatile("cp.async.wait_group 0;" ::: "memory");
        __syncthreads();

        // Prefetch next B tile into the alternate buffer
        if (kt + 1 < 8) {
            const __nv_bfloat16* gBn = g_Cbf + (size_t)(kt + 1) * 128 * D_;
            #pragma unroll
            for (int i = 0; i < 8; i++) {
                int v = i * 512 + tid;
                int r = v >> 5, c = v & 31;
                uint32_t off = (uint32_t)(r * 512) +
                               (((uint32_t)c * 16) ^ ((uint32_t)(r & 7) << 4));
                cp16(sBn + off, gBn + (size_t)v * 8);
            }
            asm volatile("cp.async.commit_group;");
        }

        const uint32_t bAddr0 = sBc + (uint32_t)b_row * 512;
        const uint32_t bAddr1 = sBc + (uint32_t)(b_row + 16) * 512;

        float acc[2][4][4];
        #pragma unroll
        for (int mi = 0; mi < 2; mi++)
            #pragma unroll
            for (int nt = 0; nt < 4; nt++)
                #pragma unroll
                for (int e = 0; e < 4; e++) acc[mi][nt][e] = 0.f;

        // 2-stage register fragment pipeline over ks
        uint32_t afb[2][2][4], bfb[2][2][4];
        {
            uint32_t ka = (uint32_t)a_kb ^ a_swz;
            uint32_t kb = (uint32_t)b_kb ^ b_swz;
            ldm_x4(afb[0][0], aAddr0 + ka);
            ldm_x4(afb[0][1], aAddr1 + ka);
            ldm_x4(bfb[0][0], bAddr0 + kb);
            ldm_x4(bfb[0][1], bAddr1 + kb);
        }
        #pragma unroll
        for (int ks = 0; ks < 16; ks++) {
            const int cur = ks & 1, nxt = cur ^ 1;
            if (ks < 15) {
                uint32_t ka = ((uint32_t)((ks + 1) * 32 + a_kb)) ^ a_swz;
                uint32_t kb = ((uint32_t)((ks + 1) * 32 + b_kb)) ^ b_swz;
                ldm_x4(afb[nxt][0], aAddr0 + ka);
                ldm_x4(afb[nxt][1], aAddr1 + ka);
                ldm_x4(bfb[nxt][0], bAddr0 + kb);
                ldm_x4(bfb[nxt][1], bAddr1 + kb);
            }
            #pragma unroll
            for (int mi = 0; mi < 2; mi++)
                #pragma unroll
                for (int nt = 0; nt < 4; nt++)
                    mma_bf16(acc[mi][nt], afb[cur][mi],
                             bfb[cur][nt >> 1][(nt & 1) * 2],
                             bfb[cur][nt >> 1][(nt & 1) * 2 + 1]);
        }

        // Scores IN PLACE: acc <- cn[k] - 2*acc. Update per-pixel running min.
        #pragma unroll
        for (int mi = 0; mi < 2; mi++) {
            float m0 = 3.4e38f, m1 = 3.4e38f;
            #pragma unroll
            for (int nt = 0; nt < 4; nt++) {
                int c0 = c0b + nt * 8;
                float cn0 = s_cn[kt * 128 + c0], cn1 = s_cn[kt * 128 + c0 + 1];
                acc[mi][nt][0] = fmaf(-2.f, acc[mi][nt][0], cn0);
                acc[mi][nt][1] = fmaf(-2.f, acc[mi][nt][1], cn1);
                acc[mi][nt][2] = fmaf(-2.f, acc[mi][nt][2], cn0);
                acc[mi][nt][3] = fmaf(-2.f, acc[mi][nt][3], cn1);
                m0 = fminf(m0, fminf(acc[mi][nt][0], acc[mi][nt][1]));
                m1 = fminf(m1, fminf(acc[mi][nt][2], acc[mi][nt][3]));
            }
            m0 = fminf(m0, __shfl_xor_sync(0xFFFFFFFFu, m0, 1));
            m0 = fminf(m0, __shfl_xor_sync(0xFFFFFFFFu, m0, 2));
            m1 = fminf(m1, __shfl_xor_sync(0xFFFFFFFFu, m1, 1));
            m1 = fminf(m1, __shfl_xor_sync(0xFFFFFFFFu, m1, 2));
            if ((lane & 3) == 0) {
                atomicMin(&s_min[r0b + mi * 16],     float_to_ordered(m0));
                atomicMin(&s_min[r0b + mi * 16 + 8], float_to_ordered(m1));
            }
        }
        // NO syncthreads: stale (larger) min still yields a candidate superset.

        // Emit candidates vs running min (ballot-aggregated smem counter)
        const unsigned pixb = (unsigned)(pt * 128);
        #pragma unroll
        for (int mi = 0; mi < 2; mi++) {
            int r0 = r0b + mi * 16;
            float thr0 = ordered_to_float(s_min[r0]) + EPS_MARGIN;
            float thr1 = ordered_to_float(s_min[r0 + 8]) + EPS_MARGIN;
            #pragma unroll
            for (int nt = 0; nt < 4; nt++) {
                int c0 = c0b + nt * 8;
                #pragma unroll
                for (int e = 0; e < 4; e++) {
                    float v = acc[mi][nt][e];
                    float thr = (e < 2) ? thr0 : thr1;
                    bool pred = (v <= thr);
                    unsigned mask = __ballot_sync(0xFFFFFFFFu, pred);
                    if (mask) {
                        int leader = __ffs(mask) - 1;
                        unsigned widx = 0;
                        if (lane == leader)
                            widx = atomicAdd(&s_cnt, (unsigned)__popc(mask));
                        widx = __shfl_sync(0xFFFFFFFFu, widx, leader);
                        if (pred) {
                            unsigned slot = widx + __popc(mask & ((1u << lane) - 1u));
                            unsigned row = (unsigned)(r0 + ((e < 2) ? 0 : 8));
                            unsigned k = (unsigned)(kt * 128 + c0 + (e & 1));
                            unsigned long long entry =
                                ((unsigned long long)__float_as_uint(v) << 32) |
                                ((unsigned long long)(pixb + row) << 10) | k;
                            if (slot < STAGE_CAP) stage[slot] = entry;
                            else {
                                unsigned gs = atomicAdd(&g_ncand, 1u);
                                if (gs < CAND_CAP) g_cand[gs] = entry;
                            }
                        }
                    }
                }
            }
        }
    }
    __syncthreads();

    // Final flush, pass 1: count final-filtered candidates per pixel
    const unsigned total = min(s_cnt, (unsigned)STAGE_CAP);
    const bool oflow = (s_cnt > (unsigned)STAGE_CAP);
    for (unsigned i = tid; i < total; i += 512) {
        unsigned long long e = stage[i];
        float v = __uint_as_float((unsigned)(e >> 32));
        unsigned row = ((unsigned)e >> 10) & 127u;
        if (v <= ordered_to_float(s_min[row]) + EPS_MARGIN)
            atomicAdd(&s_pcount[row], 1u);
    }
    __syncthreads();

    // Pass 2: singles -> direct g_best write (full score A + filter score);
    //         multis -> s_multi index list for in-CTA exact rescore.
    const unsigned rounded = (total + 511u) & ~511u;
    for (unsigned i = tid; i < rounded; i += 512) {
        bool pred = false;
        unsigned long long e = 0;
        if (i < total) {
            e = stage[i];
            float v = __uint_as_float((unsigned)(e >> 32));
            unsigned low = (unsigned)e;
            unsigned row = (low >> 10) & 127u;
            if (v <= ordered_to_float(s_min[row]) + EPS_MARGIN) {
                if (s_pcount[row] == 1u && !oflow) {
                    unsigned pix = low >> 10, k = low & 1023u;
                    float full = __fadd_rn(s_A[row], v);   // A + (cn - 2dot)
                    unsigned long long key =
                        ((unsigned long long)float_to_ordered(full) << 32) |
                        (unsigned long long)k;
                    atomicMin(&g_best[pix], key);
                } else {
                    pred = true;
                }
            }
        }
        unsigned mask = __ballot_sync(0xFFFFFFFFu, pred);
        if (mask) {
            int leader = __ffs(mask) - 1;
            unsigned bidx = 0;
            if (lane == leader) bidx = atomicAdd(&s_mcnt, (unsigned)__popc(mask));
            bidx = __shfl_sync(0xFFFFFFFFu, bidx, leader);
            if (pred) {
                unsigned dst = bidx + __popc(mask & ((1u << lane) - 1u));
                if (dst < MULTI_CAP && !oflow) {
                    s_multi[dst] = i;
                } else {
                    unsigned gs = atomicAdd(&g_ncand, 1u);
                    if (gs < CAND_CAP) g_cand[gs] = e;
                }
            }
        }
    }
    __syncthreads();

    // In-CTA exact rescore of multis: one warp per entry.
    // score = fl(fl(A - 2*dot) + cn) — Round-2-validated chain, fp32 inputs.
    const unsigned mtotal = oflow ? 0u : min(s_mcnt, (unsigned)MULTI_CAP);
    for (unsigned m = wid; m < mtotal; m += 16) {
        unsigned long long e = stage[s_multi[m]];
        unsigned low = (unsigned)e;
        unsigned pix = low >> 10, k = low & 1023u;
        unsigned row = pix & 127u;

        const float4* xr = reinterpret_cast<const float4*>(g_Xt + (size_t)pix * D_);
        const float4* cr = reinterpret_cast<const float4*>(C + (size_t)k * D_);
        float dot = 0.f;
        #pragma unroll
        for (int t = 0; t < 2; t++) {
            float4 xv = xr[lane * 2 + t];
            float4 cv = cr[lane * 2 + t];
            dot = fmaf(xv.x, cv.x, dot);
            dot = fmaf(xv.y, cv.y, dot);
            dot = fmaf(xv.z, cv.z, dot);
            dot = fmaf(xv.w, cv.w, dot);
        }
        #pragma unroll
        for (int o = 16; o > 0; o >>= 1) dot += __shfl_down_sync(0xFFFFFFFFu, dot, o);
        if (lane == 0) {
            float sc = __fadd_rn(__fadd_rn(s_A[row], __fmul_rn(-2.0f, dot)), s_cn[k]);
            unsigned long long key =
                ((unsigned long long)float_to_ordered(sc) << 32) | (unsigned long long)k;
            atomicMin(&g_best[pix], key);
        }
    }
}

// ---------------------------------------------------------------------------
// Kernel 3: overflow-fallback exact rescore (normally g_ncand == 0).
// ---------------------------------------------------------------------------
__global__ __launch_bounds__(256)
void rescore_kernel(const float* __restrict__ C) {
    const unsigned int count = min(g_ncand, (unsigned)CAND_CAP);
    const int lane = threadIdx.x & 31;
    const unsigned gw = (blockIdx.x * blockDim.x + threadIdx.x) >> 5;
    const unsigned nw = (gridDim.x * blockDim.x) >> 5;

    for (unsigned i = gw; i < count; i += nw) {
        unsigned long long e = g_cand[i];
        unsigned low = (unsigned)e;
        unsigned pix = low >> 10, k = low & 1023u;

        const float4* xr = reinterpret_cast<const float4*>(g_Xt + (size_t)pix * D_);
        const float4* cr = reinterpret_cast<const float4*>(C + (size_t)k * D_);
        float dot = 0.f;
        #pragma unroll
        for (int t = 0; t < 2; t++) {
            float4 xv = xr[lane * 2 + t];
            float4 cv = cr[lane * 2 + t];
            dot = fmaf(xv.x, cv.x, dot);
            dot = fmaf(xv.y, cv.y, dot);
            dot = fmaf(xv.z, cv.z, dot);
            dot = fmaf(xv.w, cv.w, dot);
        }
        #pragma unroll
        for (int o = 16; o > 0; o >>= 1) dot += __shfl_down_sync(0xFFFFFFFFu, dot, o);
        if (lane == 0) {
            float sc = __fadd_rn(__fadd_rn(g_A[pix], __fmul_rn(-2.0f, dot)), g_cn[k]);
            unsigned long long key =
                ((unsigned long long)float_to_ordered(sc) << 32) | (unsigned long long)k;
            atomicMin(&g_best[pix], key);
        }
    }
}

// ---------------------------------------------------------------------------
// Kernel 4: gather output (NCHW), smem-staged code rows.
// ---------------------------------------------------------------------------
__global__ __launch_bounds__(256)
void gather_kernel(const float* __restrict__ C, float* __restrict__ out) {
    __shared__ float rows[32][260];
    __shared__ int s_k[32];
    const int tid = threadIdx.x, lane = tid & 31, wid = tid >> 5;
    const int b  = blockIdx.x >> 5;
    const int pB = (blockIdx.x & 31) * 32;

    if (tid < 32)
        s_k[tid] = (int)(unsigned int)(g_best[b * HW_ + pB + tid] & 1023u);
    __syncthreads();

    const float4* C4 = reinterpret_cast<const float4*>(C);
    #pragma unroll
    for (int i = 0; i < 8; i++) {
        int idx = i * 256 + tid;          // 0..2047
        int r = idx >> 6, c = idx & 63;
        float4 v = C4[s_k[r] * 64 + c];
        *reinterpret_cast<float4*>(&rows[r][c * 4]) = v;
    }
    __syncthreads();

    float* ob = out + (size_t)b * D_ * HW_ + pB;
    #pragma unroll
    for (int it = 0; it < 32; it++) {
        int d = it * 8 + wid;
        ob[(size_t)d * HW_ + lane] = rows[lane][d];
    }
}

// ---------------------------------------------------------------------------
// Kernel 5: loss = 1.25 * sum(per-pixel min scores) / NELM, from g_best.
// ---------------------------------------------------------------------------
__global__ __launch_bounds__(1024)
void finalize_kernel(float* __restrict__ out, int loss_idx) {
    __shared__ double red[1024];
    double s = 0.0;
    for (int i = threadIdx.x; i < NPIX; i += 1024)
        s += (double)ordered_to_float((unsigned)(g_best[i] >> 32));
    red[threadIdx.x] = s;
    __syncthreads();
    for (int o = 512; o > 0; o >>= 1) {
        if (threadIdx.x < o) red[threadIdx.x] += red[threadIdx.x + o];
        __syncthreads();
    }
    if (threadIdx.x == 0)
        out[loss_idx] = (float)(1.25 * red[0] / (double)NELM);
}

// ---------------------------------------------------------------------------
extern "C" void kernel_launch(void* const* d_in, const int* in_sizes, int n_in,
                              void* d_out, int out_size) {
    const float* X = (const float*)d_in[0];   // [64,256,32,32] f32 NCHW
    const float* C = (const float*)d_in[1];   // [1024,256] f32
    float* out = (float*)d_out;

    static const int SMEM_BYTES = 196608 + 1024;   // A + 2xB (+ align slack)
    cudaFuncSetAttribute(vq_mma_kernel,
                         cudaFuncAttributeMaxDynamicSharedMemorySize, SMEM_BYTES);

    prologue_kernel<<<16672, 256>>>(X, C);
    vq_mma_kernel<<<NPIX / 128, 512, SMEM_BYTES>>>(C);
    rescore_kernel<<<128, 256>>>(C);
    gather_kernel<<<NPIX / 32, 256>>>(C, out);
    if (out_size > NELM) {
        finalize_kernel<<<1, 1024>>>(out, out_size - 1);
    }
}

// round 12
// speedup vs baseline: 1.1036x; 1.1036x over previous
#include <cuda_runtime.h>
#include <cuda_bf16.h>
#include <cstdint>

// Problem constants (fixed for this dataset)
#define B_   64
#define D_   256
#define HW_  1024            // 32*32
#define K_   1024            // num embeddings
#define NPIX (B_ * HW_)      // 65536
#define NELM (B_ * D_ * HW_) // 16777216
#define CAND_CAP 1048576
#define EPS_MARGIN 5e-3f
#define STAGE_CAP 2816
#define MULTI_CAP 1024

// ---------------------------------------------------------------------------
// Scratch (device globals; no cudaMalloc allowed)
// ---------------------------------------------------------------------------
__device__ unsigned long long g_best[NPIX];   // packed (orderable_score<<32)|k
__device__ float g_cn[K_];                    // |c_k|^2 (exact sequential chain)
__device__ float g_A[NPIX];                   // |x_n|^2 (exact sequential chain)
__device__ float g_Xt[NPIX * D_];             // X transposed: [pix][d] fp32
__device__ __nv_bfloat16 g_Xt_bf[NPIX * D_];  // bf16 copy
__device__ __nv_bfloat16 g_Cbf[K_ * D_];      // codebook bf16
__device__ unsigned long long g_cand[CAND_CAP]; // overflow-only fallback
__device__ unsigned int g_ncand;

__device__ __forceinline__ unsigned int float_to_ordered(float f) {
    unsigned int u = __float_as_uint(f);
    return (u & 0x80000000u) ? ~u : (u | 0x80000000u);
}
__device__ __forceinline__ float ordered_to_float(unsigned int o) {
    unsigned int u = (o & 0x80000000u) ? (o & 0x7FFFFFFFu) : ~o;
    return __uint_as_float(u);
}

__device__ __forceinline__ uint32_t smem_u32(const void* p) {
    uint32_t a;
    asm("{ .reg .u64 t; cvta.to.shared.u64 t, %1; cvt.u32.u64 %0, t; }"
        : "=r"(a) : "l"(p));
    return a;
}

// cp.async 16B (sm_80+, legal on plain sm_103 target)
__device__ __forceinline__ void cp16(uint32_t saddr, const void* g) {
    asm volatile("cp.async.cg.shared.global [%0], [%1], 16;"
                 :: "r"(saddr), "l"(g) : "memory");
}

// ldmatrix x4 (non-transposed, b16)
__device__ __forceinline__ void ldm_x4(uint32_t* r, uint32_t addr) {
    asm volatile("ldmatrix.sync.aligned.m8n8.x4.shared.b16 {%0,%1,%2,%3}, [%4];"
                 : "=r"(r[0]), "=r"(r[1]), "=r"(r[2]), "=r"(r[3]) : "r"(addr));
}

// bf16 HMMA m16n8k16, f32 accumulate (sm_80+)
__device__ __forceinline__ void mma_bf16(float* c, const uint32_t* a,
                                         uint32_t b0, uint32_t b1) {
    asm volatile(
        "mma.sync.aligned.m16n8k16.row.col.f32.bf16.bf16.f32 "
        "{%0,%1,%2,%3}, {%4,%5,%6,%7}, {%8,%9}, {%0,%1,%2,%3};"
        : "+f"(c[0]), "+f"(c[1]), "+f"(c[2]), "+f"(c[3])
        : "r"(a[0]), "r"(a[1]), "r"(a[2]), "r"(a[3]), "r"(b0), "r"(b1));
}

// ---------------------------------------------------------------------------
// Kernel 1: |c_k|^2 (exact sequential chain) + bf16 convert, coalesced.
// ---------------------------------------------------------------------------
__global__ __launch_bounds__(256)
void cn_cbf_kernel(const float* __restrict__ C) {
    __shared__ float rows[32][257];
    const int tid = threadIdx.x;
    const int kb = blockIdx.x * 32;
    if (blockIdx.x == 0 && tid == 0) g_ncand = 0;

    const float4* C4 = reinterpret_cast<const float4*>(C + (size_t)kb * D_);
    uint2* B2 = reinterpret_cast<uint2*>(g_Cbf + (size_t)kb * D_);
    #pragma unroll
    for (int i = 0; i < 8; i++) {
        int idx = i * 256 + tid;          // float4 index: 0..2047
        int r = idx >> 6, c = idx & 63;   // 64 float4 per row
        float4 v = C4[idx];
        rows[r][c * 4 + 0] = v.x;
        rows[r][c * 4 + 1] = v.y;
        rows[r][c * 4 + 2] = v.z;
        rows[r][c * 4 + 3] = v.w;
        __nv_bfloat162 h01 = __floats2bfloat162_rn(v.x, v.y);
        __nv_bfloat162 h23 = __floats2bfloat162_rn(v.z, v.w);
        uint2 pk;
        pk.x = *reinterpret_cast<unsigned int*>(&h01);
        pk.y = *reinterpret_cast<unsigned int*>(&h23);
        B2[idx] = pk;
    }
    __syncthreads();
    if (tid < 32) {
        float s = 0.f;
        #pragma unroll 8
        for (int d = 0; d < D_; d++) {
            float v = rows[tid][d];
            s = __fadd_rn(s, __fmul_rn(v, v));
        }
        g_cn[kb + tid] = s;
    }
}

// ---------------------------------------------------------------------------
// Kernel 2: |x_p|^2 (exact sequential chain). 256x256, coalesced.
// ---------------------------------------------------------------------------
__global__ __launch_bounds__(256)
void a_kernel(const float* __restrict__ X) {
    const int pix = blockIdx.x * 256 + threadIdx.x;
    const int b = pix >> 10, p = pix & 1023;
    const float* Xb = X + (size_t)b * D_ * HW_ + p;
    float s = 0.f;
    #pragma unroll 8
    for (int d = 0; d < D_; d++) {
        float v = Xb[(size_t)d * HW_];
        s = __fadd_rn(s, __fmul_rn(v, v));
    }
    g_A[pix] = s;
}

// ---------------------------------------------------------------------------
// Kernel 3: transpose X NCHW [b][d][p] -> pixel-major [pix][d], f32+bf16
// ---------------------------------------------------------------------------
__global__ __launch_bounds__(256)
void transpose_kernel(const float* __restrict__ X) {
    __shared__ float t[32][33];
    const int b  = blockIdx.z;
    const int dB = blockIdx.y * 32;
    const int pB = blockIdx.x * 32;
    const int tx = threadIdx.x;       // 0..31
    const int ty = threadIdx.y;       // 0..7

    const float* src = X + ((size_t)b * D_ + dB) * HW_ + pB;
    #pragma unroll
    for (int i = 0; i < 32; i += 8)
        t[ty + i][tx] = src[(size_t)(ty + i) * HW_ + tx];
    __syncthreads();

    const size_t obase = ((size_t)(b * HW_ + pB)) * D_ + dB;
    #pragma unroll
    for (int i = 0; i < 32; i += 8) {
        int row = ty + i;
        float v = t[tx][row];
        g_Xt[obase + (size_t)row * D_ + tx] = v;
        g_Xt_bf[obase + (size_t)row * D_ + tx] = __float2bfloat16(v);
    }
}

// ---------------------------------------------------------------------------
// Kernel 4: persistent-A bf16 HMMA GEMM, 128 pixels x ALL 1024 codes per CTA.
// 512 threads / 16 warps, 32x32 warp tile, 2-stage register fragment pipeline.
// Per-thread divergent emission (R10-validated — predicate fires ~0.3%, so
// aggregation costs more than it saves). Singles write g_best directly with
// full score A + (cn-2dot); multis exactly rescored IN-CTA (Round-2 chain).
// ---------------------------------------------------------------------------
__global__ __launch_bounds__(512, 1)
void vq_mma_kernel(const float* __restrict__ C) {
    extern __shared__ char dsm_raw[];
    __shared__ float s_cn[K_];
    __shared__ float s_A[128];
    __shared__ unsigned int s_min[128];
    __shared__ unsigned int s_pcount[128];
    __shared__ unsigned long long stage[STAGE_CAP];
    __shared__ unsigned int s_multi[MULTI_CAP];
    __shared__ unsigned int s_cnt, s_mcnt;

    const int tid = threadIdx.x, lane = tid & 31, wid = tid >> 5;
    const int pt = blockIdx.x;   // 0..511 pixel tiles (128 pixels each)

    const uint32_t s0 = smem_u32(dsm_raw);
    const uint32_t base = (s0 + 1023) & ~1023u;
    const uint32_t sA = base;
    const uint32_t sB0 = base + 65536, sB1 = base + 131072;

    #pragma unroll
    for (int i = 0; i < 2; i++) s_cn[tid + i * 512] = g_cn[tid + i * 512];
    if (tid < 128) {
        s_min[tid] = 0xFFFFFFFFu;
        s_pcount[tid] = 0u;
        s_A[tid] = g_A[pt * 128 + tid];
        g_best[pt * 128 + tid] = 0xFFFFFFFFFFFFFFFFull;
    }
    if (tid == 0) { s_cnt = 0; s_mcnt = 0; }

    // Stage A (once) + B tile 0
    const __nv_bfloat16* gA = g_Xt_bf + (size_t)pt * 128 * D_;
    #pragma unroll
    for (int i = 0; i < 8; i++) {
        int v = i * 512 + tid;             // 0..4095 16B chunks
        int r = v >> 5, c = v & 31;
        uint32_t off = (uint32_t)(r * 512) + (((uint32_t)c * 16) ^ ((uint32_t)(r & 7) << 4));
        cp16(sA + off, gA + (size_t)v * 8);
        cp16(sB0 + off, g_Cbf + (size_t)v * 8);
    }
    asm volatile("cp.async.commit_group;");

    // Warp tiling: 4 (m) x 4 (n), 32x32 per warp
    const int wm = (wid & 3) * 32;
    const int wn = (wid >> 2) * 32;
    const int a_row = wm + (lane & 15);
    const uint32_t a_swz = (uint32_t)((a_row & 7) << 4);
    const int a_kb = (lane >> 4) * 16;
    const int b_row = wn + ((lane & 7) | ((lane & 16) >> 1));
    const uint32_t b_swz = (uint32_t)((b_row & 7) << 4);
    const int b_kb = ((lane >> 3) & 1) * 16;

    const int r0b = wm + (lane >> 2);          // score row base (mi adds 16)
    const int c0b = wn + (lane & 3) * 2;       // score col base (nt adds 8)

    const uint32_t aAddr0 = sA + (uint32_t)a_row * 512;
    const uint32_t aAddr1 = sA + (uint32_t)(a_row + 16) * 512;

    for (int kt = 0; kt < 8; kt++) {
        const uint32_t sBc = (kt & 1) ? sB1 : sB0;
        const uint32_t sBn = (kt & 1) ? sB0 : sB1;

        asm volatile("cp.async.wait_group 0;" ::: "memory");
        __syncthreads();

        // Prefetch next B tile into the alternate buffer
        if (kt + 1 < 8) {
            const __nv_bfloat16* gBn = g_Cbf + (size_t)(kt + 1) * 128 * D_;
            #pragma unroll
            for (int i = 0; i < 8; i++) {
                int v = i * 512 + tid;
                int r = v >> 5, c = v & 31;
                uint32_t off = (uint32_t)(r * 512) +
                               (((uint32_t)c * 16) ^ ((uint32_t)(r & 7) << 4));
                cp16(sBn + off, gBn + (size_t)v * 8);
            }
            asm volatile("cp.async.commit_group;");
        }

        const uint32_t bAddr0 = sBc + (uint32_t)b_row * 512;
        const uint32_t bAddr1 = sBc + (uint32_t)(b_row + 16) * 512;

        float acc[2][4][4];
        #pragma unroll
        for (int mi = 0; mi < 2; mi++)
            #pragma unroll
            for (int nt = 0; nt < 4; nt++)
                #pragma unroll
                for (int e = 0; e < 4; e++) acc[mi][nt][e] = 0.f;

        // 2-stage register fragment pipeline over ks
        uint32_t afb[2][2][4], bfb[2][2][4];
        {
            uint32_t ka = (uint32_t)a_kb ^ a_swz;
            uint32_t kb = (uint32_t)b_kb ^ b_swz;
            ldm_x4(afb[0][0], aAddr0 + ka);
            ldm_x4(afb[0][1], aAddr1 + ka);
            ldm_x4(bfb[0][0], bAddr0 + kb);
            ldm_x4(bfb[0][1], bAddr1 + kb);
        }
        #pragma unroll
        for (int ks = 0; ks < 16; ks++) {
            const int cur = ks & 1, nxt = cur ^ 1;
            if (ks < 15) {
                uint32_t ka = ((uint32_t)((ks + 1) * 32 + a_kb)) ^ a_swz;
                uint32_t kb = ((uint32_t)((ks + 1) * 32 + b_kb)) ^ b_swz;
                ldm_x4(afb[nxt][0], aAddr0 + ka);
                ldm_x4(afb[nxt][1], aAddr1 + ka);
                ldm_x4(bfb[nxt][0], bAddr0 + kb);
                ldm_x4(bfb[nxt][1], bAddr1 + kb);
            }
            #pragma unroll
            for (int mi = 0; mi < 2; mi++)
                #pragma unroll
                for (int nt = 0; nt < 4; nt++)
                    mma_bf16(acc[mi][nt], afb[cur][mi],
                             bfb[cur][nt >> 1][(nt & 1) * 2],
                             bfb[cur][nt >> 1][(nt & 1) * 2 + 1]);
        }

        // Scores IN PLACE: acc <- cn[k] - 2*acc. Update per-pixel running min.
        #pragma unroll
        for (int mi = 0; mi < 2; mi++) {
            float m0 = 3.4e38f, m1 = 3.4e38f;
            #pragma unroll
            for (int nt = 0; nt < 4; nt++) {
                int c0 = c0b + nt * 8;
                float cn0 = s_cn[kt * 128 + c0], cn1 = s_cn[kt * 128 + c0 + 1];
                acc[mi][nt][0] = fmaf(-2.f, acc[mi][nt][0], cn0);
                acc[mi][nt][1] = fmaf(-2.f, acc[mi][nt][1], cn1);
                acc[mi][nt][2] = fmaf(-2.f, acc[mi][nt][2], cn0);
                acc[mi][nt][3] = fmaf(-2.f, acc[mi][nt][3], cn1);
                m0 = fminf(m0, fminf(acc[mi][nt][0], acc[mi][nt][1]));
                m1 = fminf(m1, fminf(acc[mi][nt][2], acc[mi][nt][3]));
            }
            m0 = fminf(m0, __shfl_xor_sync(0xFFFFFFFFu, m0, 1));
            m0 = fminf(m0, __shfl_xor_sync(0xFFFFFFFFu, m0, 2));
            m1 = fminf(m1, __shfl_xor_sync(0xFFFFFFFFu, m1, 1));
            m1 = fminf(m1, __shfl_xor_sync(0xFFFFFFFFu, m1, 2));
            if ((lane & 3) == 0) {
                atomicMin(&s_min[r0b + mi * 16],     float_to_ordered(m0));
                atomicMin(&s_min[r0b + mi * 16 + 8], float_to_ordered(m1));
            }
        }
        // NO syncthreads: stale (larger) min still yields a candidate superset.

        // Emit candidates vs running min (per-thread, rare-divergent)
        const unsigned pixb = (unsigned)(pt * 128);
        #pragma unroll
        for (int mi = 0; mi < 2; mi++) {
            int r0 = r0b + mi * 16;
            float thr0 = ordered_to_float(s_min[r0]) + EPS_MARGIN;
            float thr1 = ordered_to_float(s_min[r0 + 8]) + EPS_MARGIN;
            #pragma unroll
            for (int nt = 0; nt < 4; nt++) {
                int c0 = c0b + nt * 8;
                #pragma unroll
                for (int e = 0; e < 4; e++) {
                    float v = acc[mi][nt][e];
                    float thr = (e < 2) ? thr0 : thr1;
                    if (v <= thr) {
                        unsigned row = (unsigned)(r0 + ((e < 2) ? 0 : 8));
                        unsigned k = (unsigned)(kt * 128 + c0 + (e & 1));
                        unsigned long long entry =
                            ((unsigned long long)__float_as_uint(v) << 32) |
                            ((unsigned long long)(pixb + row) << 10) | k;
                        unsigned slot = atomicAdd(&s_cnt, 1u);
                        if (slot < STAGE_CAP) stage[slot] = entry;
                        else {
                            unsigned gs = atomicAdd(&g_ncand, 1u);
                            if (gs < CAND_CAP) g_cand[gs] = entry;
                        }
                    }
                }
            }
        }
    }
    __syncthreads();

    // Final flush, pass 1: count final-filtered candidates per pixel
    const unsigned total = min(s_cnt, (unsigned)STAGE_CAP);
    const bool oflow = (s_cnt > (unsigned)STAGE_CAP);
    for (unsigned i = tid; i < total; i += 512) {
        unsigned long long e = stage[i];
        float v = __uint_as_float((unsigned)(e >> 32));
        unsigned row = ((unsigned)e >> 10) & 127u;
        if (v <= ordered_to_float(s_min[row]) + EPS_MARGIN)
            atomicAdd(&s_pcount[row], 1u);
    }
    __syncthreads();

    // Pass 2: singles -> direct g_best write (full score A + filter score);
    //         multis -> s_multi index list for in-CTA exact rescore.
    const unsigned rounded = (total + 511u) & ~511u;
    for (unsigned i = tid; i < rounded; i += 512) {
        bool pred = false;
        unsigned long long e = 0;
        if (i < total) {
            e = stage[i];
            float v = __uint_as_float((unsigned)(e >> 32));
            unsigned low = (unsigned)e;
            unsigned row = (low >> 10) & 127u;
            if (v <= ordered_to_float(s_min[row]) + EPS_MARGIN) {
                if (s_pcount[row] == 1u && !oflow) {
                    unsigned pix = low >> 10, k = low & 1023u;
                    float full = __fadd_rn(s_A[row], v);   // A + (cn - 2dot)
                    unsigned long long key =
                        ((unsigned long long)float_to_ordered(full) << 32) |
                        (unsigned long long)k;
                    atomicMin(&g_best[pix], key);
                } else {
                    pred = true;
                }
            }
        }
        unsigned mask = __ballot_sync(0xFFFFFFFFu, pred);
        if (mask) {
            int leader = __ffs(mask) - 1;
            unsigned bidx = 0;
            if (lane == leader) bidx = atomicAdd(&s_mcnt, (unsigned)__popc(mask));
            bidx = __shfl_sync(0xFFFFFFFFu, bidx, leader);
            if (pred) {
                unsigned dst = bidx + __popc(mask & ((1u << lane) - 1u));
                if (dst < MULTI_CAP && !oflow) {
                    s_multi[dst] = i;
                } else {
                    unsigned gs = atomicAdd(&g_ncand, 1u);
                    if (gs < CAND_CAP) g_cand[gs] = e;
                }
            }
        }
    }
    __syncthreads();

    // In-CTA exact rescore of multis: one warp per entry.
    // score = fl(fl(A - 2*dot) + cn) — Round-2-validated chain, fp32 inputs.
    const unsigned mtotal = oflow ? 0u : min(s_mcnt, (unsigned)MULTI_CAP);
    for (unsigned m = wid; m < mtotal; m += 16) {
        unsigned long long e = stage[s_multi[m]];
        unsigned low = (unsigned)e;
        unsigned pix = low >> 10, k = low & 1023u;
        unsigned row = pix & 127u;

        const float4* xr = reinterpret_cast<const float4*>(g_Xt + (size_t)pix * D_);
        const float4* cr = reinterpret_cast<const float4*>(C + (size_t)k * D_);
        float dot = 0.f;
        #pragma unroll
        for (int t = 0; t < 2; t++) {
            float4 xv = xr[lane * 2 + t];
            float4 cv = cr[lane * 2 + t];
            dot = fmaf(xv.x, cv.x, dot);
            dot = fmaf(xv.y, cv.y, dot);
            dot = fmaf(xv.z, cv.z, dot);
            dot = fmaf(xv.w, cv.w, dot);
        }
        #pragma unroll
        for (int o = 16; o > 0; o >>= 1) dot += __shfl_down_sync(0xFFFFFFFFu, dot, o);
        if (lane == 0) {
            float sc = __fadd_rn(__fadd_rn(s_A[row], __fmul_rn(-2.0f, dot)), s_cn[k]);
            unsigned long long key =
                ((unsigned long long)float_to_ordered(sc) << 32) | (unsigned long long)k;
            atomicMin(&g_best[pix], key);
        }
    }
}

// ---------------------------------------------------------------------------
// Kernel 5: overflow-fallback exact rescore (normally g_ncand == 0).
// ---------------------------------------------------------------------------
__global__ __launch_bounds__(256)
void rescore_kernel(const float* __restrict__ C) {
    const unsigned int count = min(g_ncand, (unsigned)CAND_CAP);
    const int lane = threadIdx.x & 31;
    const unsigned gw = (blockIdx.x * blockDim.x + threadIdx.x) >> 5;
    const unsigned nw = (gridDim.x * blockDim.x) >> 5;

    for (unsigned i = gw; i < count; i += nw) {
        unsigned long long e = g_cand[i];
        unsigned low = (unsigned)e;
        unsigned pix = low >> 10, k = low & 1023u;

        const float4* xr = reinterpret_cast<const float4*>(g_Xt + (size_t)pix * D_);
        const float4* cr = reinterpret_cast<const float4*>(C + (size_t)k * D_);
        float dot = 0.f;
        #pragma unroll
        for (int t = 0; t < 2; t++) {
            float4 xv = xr[lane * 2 + t];
            float4 cv = cr[lane * 2 + t];
            dot = fmaf(xv.x, cv.x, dot);
            dot = fmaf(xv.y, cv.y, dot);
            dot = fmaf(xv.z, cv.z, dot);
            dot = fmaf(xv.w, cv.w, dot);
        }
        #pragma unroll
        for (int o = 16; o > 0; o >>= 1) dot += __shfl_down_sync(0xFFFFFFFFu, dot, o);
        if (lane == 0) {
            float sc = __fadd_rn(__fadd_rn(g_A[pix], __fmul_rn(-2.0f, dot)), g_cn[k]);
            unsigned long long key =
                ((unsigned long long)float_to_ordered(sc) << 32) | (unsigned long long)k;
            atomicMin(&g_best[pix], key);
        }
    }
}

// ---------------------------------------------------------------------------
// Kernel 6: gather output (NCHW), smem-staged code rows.
// ---------------------------------------------------------------------------
__global__ __launch_bounds__(256)
void gather_kernel(const float* __restrict__ C, float* __restrict__ out) {
    __shared__ float rows[32][260];
    __shared__ int s_k[32];
    const int tid = threadIdx.x, lane = tid & 31, wid = tid >> 5;
    const int b  = blockIdx.x >> 5;
    const int pB = (blockIdx.x & 31) * 32;

    if (tid < 32)
        s_k[tid] = (int)(unsigned int)(g_best[b * HW_ + pB + tid] & 1023u);
    __syncthreads();

    const float4* C4 = reinterpret_cast<const float4*>(C);
    #pragma unroll
    for (int i = 0; i < 8; i++) {
        int idx = i * 256 + tid;          // 0..2047
        int r = idx >> 6, c = idx & 63;
        float4 v = C4[s_k[r] * 64 + c];
        *reinterpret_cast<float4*>(&rows[r][c * 4]) = v;
    }
    __syncthreads();

    float* ob = out + (size_t)b * D_ * HW_ + pB;
    #pragma unroll
    for (int it = 0; it < 32; it++) {
        int d = it * 8 + wid;
        ob[(size_t)d * HW_ + lane] = rows[lane][d];
    }
}

// ---------------------------------------------------------------------------
// Kernel 7: loss = 1.25 * sum(per-pixel min scores) / NELM, from g_best.
// ---------------------------------------------------------------------------
__global__ __launch_bounds__(1024)
void finalize_kernel(float* __restrict__ out, int loss_idx) {
    __shared__ double red[1024];
    double s = 0.0;
    for (int i = threadIdx.x; i < NPIX; i += 1024)
        s += (double)ordered_to_float((unsigned)(g_best[i] >> 32));
    red[threadIdx.x] = s;
    __syncthreads();
    for (int o = 512; o > 0; o >>= 1) {
        if (threadIdx.x < o) red[threadIdx.x] += red[threadIdx.x + o];
        __syncthreads();
    }
    if (threadIdx.x == 0)
        out[loss_idx] = (float)(1.25 * red[0] / (double)NELM);
}

// ---------------------------------------------------------------------------
extern "C" void kernel_launch(void* const* d_in, const int* in_sizes, int n_in,
                              void* d_out, int out_size) {
    const float* X = (const float*)d_in[0];   // [64,256,32,32] f32 NCHW
    const float* C = (const float*)d_in[1];   // [1024,256] f32
    float* out = (float*)d_out;

    static const int SMEM_BYTES = 196608 + 1024;   // A + 2xB (+ align slack)
    cudaFuncSetAttribute(vq_mma_kernel,
                         cudaFuncAttributeMaxDynamicSharedMemorySize, SMEM_BYTES);

    cn_cbf_kernel<<<K_ / 32, 256>>>(C);
    a_kernel<<<NPIX / 256, 256>>>(X);
    transpose_kernel<<<dim3(HW_ / 32, D_ / 32, B_), dim3(32, 8)>>>(X);
    vq_mma_kernel<<<NPIX / 128, 512, SMEM_BYTES>>>(C);
    rescore_kernel<<<128, 256>>>(C);
    gather_kernel<<<NPIX / 32, 256>>>(C, out);
    if (out_size > NELM) {
        finalize_kernel<<<1, 1024>>>(out, out_size - 1);
    }
}

// round 13
// speedup vs baseline: 1.1590x; 1.0502x over previous
#include <cuda_runtime.h>
#include <cuda_bf16.h>
#include <cstdint>

// Problem constants (fixed for this dataset)
#define B_   64
#define D_   256
#define HW_  1024            // 32*32
#define K_   1024            // num embeddings
#define NPIX (B_ * HW_)      // 65536
#define NELM (B_ * D_ * HW_) // 16777216
#define CAND_CAP 1048576
#define EPS_MARGIN 5e-3f
#define STAGE_CAP 2816

// ---------------------------------------------------------------------------
// Scratch (device globals; no cudaMalloc allowed)
// ---------------------------------------------------------------------------
__device__ unsigned long long g_best[NPIX];   // packed (orderable_score<<32)|k
__device__ float g_cn[K_];                    // |c_k|^2 (exact sequential chain)
__device__ float g_A[NPIX];                   // |x_n|^2 (exact sequential chain)
__device__ float g_Xt[NPIX * D_];             // X transposed: [pix][d] fp32
__device__ __nv_bfloat16 g_Xt_bf[NPIX * D_];  // bf16 copy
__device__ __nv_bfloat16 g_Cbf[K_ * D_];      // codebook bf16
__device__ unsigned long long g_cand[CAND_CAP]; // (score_bits<<32)|(pix<<10)|k
__device__ unsigned int g_ncand;

__device__ __forceinline__ unsigned int float_to_ordered(float f) {
    unsigned int u = __float_as_uint(f);
    return (u & 0x80000000u) ? ~u : (u | 0x80000000u);
}
__device__ __forceinline__ float ordered_to_float(unsigned int o) {
    unsigned int u = (o & 0x80000000u) ? (o & 0x7FFFFFFFu) : ~o;
    return __uint_as_float(u);
}

__device__ __forceinline__ uint32_t smem_u32(const void* p) {
    uint32_t a;
    asm("{ .reg .u64 t; cvta.to.shared.u64 t, %1; cvt.u32.u64 %0, t; }"
        : "=r"(a) : "l"(p));
    return a;
}

// cp.async 16B (sm_80+, legal on plain sm_103 target)
__device__ __forceinline__ void cp16(uint32_t saddr, const void* g) {
    asm volatile("cp.async.cg.shared.global [%0], [%1], 16;"
                 :: "r"(saddr), "l"(g) : "memory");
}

// ldmatrix x4 (non-transposed, b16)
__device__ __forceinline__ void ldm_x4(uint32_t* r, uint32_t addr) {
    asm volatile("ldmatrix.sync.aligned.m8n8.x4.shared.b16 {%0,%1,%2,%3}, [%4];"
                 : "=r"(r[0]), "=r"(r[1]), "=r"(r[2]), "=r"(r[3]) : "r"(addr));
}

// bf16 HMMA m16n8k16, f32 accumulate (sm_80+)
__device__ __forceinline__ void mma_bf16(float* c, const uint32_t* a,
                                         uint32_t b0, uint32_t b1) {
    asm volatile(
        "mma.sync.aligned.m16n8k16.row.col.f32.bf16.bf16.f32 "
        "{%0,%1,%2,%3}, {%4,%5,%6,%7}, {%8,%9}, {%0,%1,%2,%3};"
        : "+f"(c[0]), "+f"(c[1]), "+f"(c[2]), "+f"(c[3])
        : "r"(a[0]), "r"(a[1]), "r"(a[2]), "r"(a[3]), "r"(b0), "r"(b1));
}

// ---------------------------------------------------------------------------
// Kernel 1: |c_k|^2 (exact sequential chain) + bf16 convert, coalesced.
// ---------------------------------------------------------------------------
__global__ __launch_bounds__(256)
void cn_cbf_kernel(const float* __restrict__ C) {
    __shared__ float rows[32][257];
    const int tid = threadIdx.x;
    const int kb = blockIdx.x * 32;
    if (blockIdx.x == 0 && tid == 0) g_ncand = 0;

    const float4* C4 = reinterpret_cast<const float4*>(C + (size_t)kb * D_);
    uint2* B2 = reinterpret_cast<uint2*>(g_Cbf + (size_t)kb * D_);
    #pragma unroll
    for (int i = 0; i < 8; i++) {
        int idx = i * 256 + tid;          // float4 index: 0..2047
        int r = idx >> 6, c = idx & 63;   // 64 float4 per row
        float4 v = C4[idx];
        rows[r][c * 4 + 0] = v.x;
        rows[r][c * 4 + 1] = v.y;
        rows[r][c * 4 + 2] = v.z;
        rows[r][c * 4 + 3] = v.w;
        __nv_bfloat162 h01 = __floats2bfloat162_rn(v.x, v.y);
        __nv_bfloat162 h23 = __floats2bfloat162_rn(v.z, v.w);
        uint2 pk;
        pk.x = *reinterpret_cast<unsigned int*>(&h01);
        pk.y = *reinterpret_cast<unsigned int*>(&h23);
        B2[idx] = pk;
    }
    __syncthreads();
    if (tid < 32) {
        float s = 0.f;
        #pragma unroll 8
        for (int d = 0; d < D_; d++) {
            float v = rows[tid][d];
            s = __fadd_rn(s, __fmul_rn(v, v));
        }
        g_cn[kb + tid] = s;
    }
}

// ---------------------------------------------------------------------------
// Kernel 2: |x_p|^2 (exact sequential chain). 256x256, coalesced.
// ---------------------------------------------------------------------------
__global__ __launch_bounds__(256)
void a_kernel(const float* __restrict__ X) {
    const int pix = blockIdx.x * 256 + threadIdx.x;
    const int b = pix >> 10, p = pix & 1023;
    const float* Xb = X + (size_t)b * D_ * HW_ + p;
    float s = 0.f;
    #pragma unroll 8
    for (int d = 0; d < D_; d++) {
        float v = Xb[(size_t)d * HW_];
        s = __fadd_rn(s, __fmul_rn(v, v));
    }
    g_A[pix] = s;
}

// ---------------------------------------------------------------------------
// Kernel 3: transpose X NCHW [b][d][p] -> pixel-major [pix][d], f32+bf16
// ---------------------------------------------------------------------------
__global__ __launch_bounds__(256)
void transpose_kernel(const float* __restrict__ X) {
    __shared__ float t[32][33];
    const int b  = blockIdx.z;
    const int dB = blockIdx.y * 32;
    const int pB = blockIdx.x * 32;
    const int tx = threadIdx.x;       // 0..31
    const int ty = threadIdx.y;       // 0..7

    const float* src = X + ((size_t)b * D_ + dB) * HW_ + pB;
    #pragma unroll
    for (int i = 0; i < 32; i += 8)
        t[ty + i][tx] = src[(size_t)(ty + i) * HW_ + tx];
    __syncthreads();

    const size_t obase = ((size_t)(b * HW_ + pB)) * D_ + dB;
    #pragma unroll
    for (int i = 0; i < 32; i += 8) {
        int row = ty + i;
        float v = t[tx][row];
        g_Xt[obase + (size_t)row * D_ + tx] = v;
        g_Xt_bf[obase + (size_t)row * D_ + tx] = __float2bfloat16(v);
    }
}

// ---------------------------------------------------------------------------
// Kernel 4: persistent-A bf16 HMMA GEMM, 128 pixels x ALL 1024 codes per CTA.
// 512 threads / 16 warps, 32x32 warp tile, 2-stage register fragment pipeline.
// Per-thread divergent emission (predicate fires ~0.3%). Singles write g_best
// directly with full score A + (cn-2dot); multis go to g_cand for the separate
// exact-rescore kernel. (This is the R10-validated 299us configuration.)
// ---------------------------------------------------------------------------
__global__ __launch_bounds__(512, 1)
void vq_mma_kernel() {
    extern __shared__ char dsm_raw[];
    __shared__ float s_cn[K_];
    __shared__ float s_A[128];
    __shared__ unsigned int s_min[128];
    __shared__ unsigned int s_pcount[128];
    __shared__ unsigned long long stage[STAGE_CAP];
    __shared__ unsigned int s_cnt;

    const int tid = threadIdx.x, lane = tid & 31, wid = tid >> 5;
    const int pt = blockIdx.x;   // 0..511 pixel tiles (128 pixels each)

    const uint32_t s0 = smem_u32(dsm_raw);
    const uint32_t base = (s0 + 1023) & ~1023u;
    const uint32_t sA = base;
    const uint32_t sB0 = base + 65536, sB1 = base + 131072;

    #pragma unroll
    for (int i = 0; i < 2; i++) s_cn[tid + i * 512] = g_cn[tid + i * 512];
    if (tid < 128) {
        s_min[tid] = 0xFFFFFFFFu;
        s_pcount[tid] = 0u;
        s_A[tid] = g_A[pt * 128 + tid];
        g_best[pt * 128 + tid] = 0xFFFFFFFFFFFFFFFFull;
    }
    if (tid == 0) s_cnt = 0;

    // Stage A (once) + B tile 0
    const __nv_bfloat16* gA = g_Xt_bf + (size_t)pt * 128 * D_;
    #pragma unroll
    for (int i = 0; i < 8; i++) {
        int v = i * 512 + tid;             // 0..4095 16B chunks
        int r = v >> 5, c = v & 31;
        uint32_t off = (uint32_t)(r * 512) + (((uint32_t)c * 16) ^ ((uint32_t)(r & 7) << 4));
        cp16(sA + off, gA + (size_t)v * 8);
        cp16(sB0 + off, g_Cbf + (size_t)v * 8);
    }
    asm volatile("cp.async.commit_group;");

    // Warp tiling: 4 (m) x 4 (n), 32x32 per warp
    const int wm = (wid & 3) * 32;
    const int wn = (wid >> 2) * 32;
    const int a_row = wm + (lane & 15);
    const uint32_t a_swz = (uint32_t)((a_row & 7) << 4);
    const int a_kb = (lane >> 4) * 16;
    const int b_row = wn + ((lane & 7) | ((lane & 16) >> 1));
    const uint32_t b_swz = (uint32_t)((b_row & 7) << 4);
    const int b_kb = ((lane >> 3) & 1) * 16;

    const int r0b = wm + (lane >> 2);          // score row base (mi adds 16)
    const int c0b = wn + (lane & 3) * 2;       // score col base (nt adds 8)

    const uint32_t aAddr0 = sA + (uint32_t)a_row * 512;
    const uint32_t aAddr1 = sA + (uint32_t)(a_row + 16) * 512;

    for (int kt = 0; kt < 8; kt++) {
        const uint32_t sBc = (kt & 1) ? sB1 : sB0;
        const uint32_t sBn = (kt & 1) ? sB0 : sB1;

        asm volatile("cp.async.wait_group 0;" ::: "memory");
        __syncthreads();

        // Prefetch next B tile into the alternate buffer
        if (kt + 1 < 8) {
            const __nv_bfloat16* gBn = g_Cbf + (size_t)(kt + 1) * 128 * D_;
            #pragma unroll
            for (int i = 0; i < 8; i++) {
                int v = i * 512 + tid;
                int r = v >> 5, c = v & 31;
                uint32_t off = (uint32_t)(r * 512) +
                               (((uint32_t)c * 16) ^ ((uint32_t)(r & 7) << 4));
                cp16(sBn + off, gBn + (size_t)v * 8);
            }
            asm volatile("cp.async.commit_group;");
        }

        const uint32_t bAddr0 = sBc + (uint32_t)b_row * 512;
        const uint32_t bAddr1 = sBc + (uint32_t)(b_row + 16) * 512;

        float acc[2][4][4];
        #pragma unroll
        for (int mi = 0; mi < 2; mi++)
            #pragma unroll
            for (int nt = 0; nt < 4; nt++)
                #pragma unroll
                for (int e = 0; e < 4; e++) acc[mi][nt][e] = 0.f;

        // 2-stage register fragment pipeline over ks
        uint32_t afb[2][2][4], bfb[2][2][4];
        {
            uint32_t ka = (uint32_t)a_kb ^ a_swz;
            uint32_t kb = (uint32_t)b_kb ^ b_swz;
            ldm_x4(afb[0][0], aAddr0 + ka);
            ldm_x4(afb[0][1], aAddr1 + ka);
            ldm_x4(bfb[0][0], bAddr0 + kb);
            ldm_x4(bfb[0][1], bAddr1 + kb);
        }
        #pragma unroll
        for (int ks = 0; ks < 16; ks++) {
            const int cur = ks & 1, nxt = cur ^ 1;
            if (ks < 15) {
                uint32_t ka = ((uint32_t)((ks + 1) * 32 + a_kb)) ^ a_swz;
                uint32_t kb = ((uint32_t)((ks + 1) * 32 + b_kb)) ^ b_swz;
                ldm_x4(afb[nxt][0], aAddr0 + ka);
                ldm_x4(afb[nxt][1], aAddr1 + ka);
                ldm_x4(bfb[nxt][0], bAddr0 + kb);
                ldm_x4(bfb[nxt][1], bAddr1 + kb);
            }
            #pragma unroll
            for (int mi = 0; mi < 2; mi++)
                #pragma unroll
                for (int nt = 0; nt < 4; nt++)
                    mma_bf16(acc[mi][nt], afb[cur][mi],
                             bfb[cur][nt >> 1][(nt & 1) * 2],
                             bfb[cur][nt >> 1][(nt & 1) * 2 + 1]);
        }

        // Scores IN PLACE: acc <- cn[k] - 2*acc. Update per-pixel running min.
        #pragma unroll
        for (int mi = 0; mi < 2; mi++) {
            float m0 = 3.4e38f, m1 = 3.4e38f;
            #pragma unroll
            for (int nt = 0; nt < 4; nt++) {
                int c0 = c0b + nt * 8;
                float cn0 = s_cn[kt * 128 + c0], cn1 = s_cn[kt * 128 + c0 + 1];
                acc[mi][nt][0] = fmaf(-2.f, acc[mi][nt][0], cn0);
                acc[mi][nt][1] = fmaf(-2.f, acc[mi][nt][1], cn1);
                acc[mi][nt][2] = fmaf(-2.f, acc[mi][nt][2], cn0);
                acc[mi][nt][3] = fmaf(-2.f, acc[mi][nt][3], cn1);
                m0 = fminf(m0, fminf(acc[mi][nt][0], acc[mi][nt][1]));
                m1 = fminf(m1, fminf(acc[mi][nt][2], acc[mi][nt][3]));
            }
            m0 = fminf(m0, __shfl_xor_sync(0xFFFFFFFFu, m0, 1));
            m0 = fminf(m0, __shfl_xor_sync(0xFFFFFFFFu, m0, 2));
            m1 = fminf(m1, __shfl_xor_sync(0xFFFFFFFFu, m1, 1));
            m1 = fminf(m1, __shfl_xor_sync(0xFFFFFFFFu, m1, 2));
            if ((lane & 3) == 0) {
                atomicMin(&s_min[r0b + mi * 16],     float_to_ordered(m0));
                atomicMin(&s_min[r0b + mi * 16 + 8], float_to_ordered(m1));
            }
        }
        // NO syncthreads: stale (larger) min still yields a candidate superset.

        // Emit candidates vs running min (per-thread, rare-divergent)
        const unsigned pixb = (unsigned)(pt * 128);
        #pragma unroll
        for (int mi = 0; mi < 2; mi++) {
            int r0 = r0b + mi * 16;
            float thr0 = ordered_to_float(s_min[r0]) + EPS_MARGIN;
            float thr1 = ordered_to_float(s_min[r0 + 8]) + EPS_MARGIN;
            #pragma unroll
            for (int nt = 0; nt < 4; nt++) {
                int c0 = c0b + nt * 8;
                #pragma unroll
                for (int e = 0; e < 4; e++) {
                    float v = acc[mi][nt][e];
                    float thr = (e < 2) ? thr0 : thr1;
                    if (v <= thr) {
                        unsigned row = (unsigned)(r0 + ((e < 2) ? 0 : 8));
                        unsigned k = (unsigned)(kt * 128 + c0 + (e & 1));
                        unsigned long long entry =
                            ((unsigned long long)__float_as_uint(v) << 32) |
                            ((unsigned long long)(pixb + row) << 10) | k;
                        unsigned slot = atomicAdd(&s_cnt, 1u);
                        if (slot < STAGE_CAP) stage[slot] = entry;
                        else {
                            unsigned gs = atomicAdd(&g_ncand, 1u);
                            if (gs < CAND_CAP) g_cand[gs] = entry;
                        }
                    }
                }
            }
        }
    }
    __syncthreads();

    // Final flush, pass 1: count final-filtered candidates per pixel
    const unsigned total = min(s_cnt, (unsigned)STAGE_CAP);
    const bool oflow = (s_cnt > (unsigned)STAGE_CAP);
    for (unsigned i = tid; i < total; i += 512) {
        unsigned long long e = stage[i];
        float v = __uint_as_float((unsigned)(e >> 32));
        unsigned row = ((unsigned)e >> 10) & 127u;
        if (v <= ordered_to_float(s_min[row]) + EPS_MARGIN)
            atomicAdd(&s_pcount[row], 1u);
    }
    __syncthreads();

    // Pass 2: singles -> direct g_best write (full score A + filter score);
    //         multis -> g_cand for exact rescoring.
    const unsigned rounded = (total + 511u) & ~511u;
    for (unsigned i = tid; i < rounded; i += 512) {
        bool pred = false;
        unsigned long long e = 0;
        if (i < total) {
            e = stage[i];
            float v = __uint_as_float((unsigned)(e >> 32));
            unsigned low = (unsigned)e;
            unsigned row = (low >> 10) & 127u;
            if (v <= ordered_to_float(s_min[row]) + EPS_MARGIN) {
                if (s_pcount[row] == 1u && !oflow) {
                    unsigned pix = low >> 10, k = low & 1023u;
                    float full = __fadd_rn(s_A[row], v);   // A + (cn - 2dot)
                    unsigned long long key =
                        ((unsigned long long)float_to_ordered(full) << 32) |
                        (unsigned long long)k;
                    atomicMin(&g_best[pix], key);
                } else {
                    pred = true;
                }
            }
        }
        unsigned mask = __ballot_sync(0xFFFFFFFFu, pred);
        if (mask) {
            int leader = __ffs(mask) - 1;
            unsigned bidx = 0;
            if (lane == leader) bidx = atomicAdd(&g_ncand, (unsigned)__popc(mask));
            bidx = __shfl_sync(0xFFFFFFFFu, bidx, leader);
            if (pred) {
                unsigned dst = bidx + __popc(mask & ((1u << lane) - 1u));
                if (dst < CAND_CAP) g_cand[dst] = e;
            }
        }
    }
}

// ---------------------------------------------------------------------------
// Kernel 5: exact fp32 rescore of multi-candidate entries (one warp each).
// score = fl(fl(A - 2*dot) + cn)  — the Round-2-validated rounding chain.
// ---------------------------------------------------------------------------
__global__ __launch_bounds__(256)
void rescore_kernel(const float* __restrict__ C) {
    const unsigned int count = min(g_ncand, (unsigned)CAND_CAP);
    const int lane = threadIdx.x & 31;
    const unsigned gw = (blockIdx.x * blockDim.x + threadIdx.x) >> 5;
    const unsigned nw = (gridDim.x * blockDim.x) >> 5;

    for (unsigned i = gw; i < count; i += nw) {
        unsigned long long e = g_cand[i];
        unsigned low = (unsigned)e;
        unsigned pix = low >> 10, k = low & 1023u;

        const float4* xr = reinterpret_cast<const float4*>(g_Xt + (size_t)pix * D_);
        const float4* cr = reinterpret_cast<const float4*>(C + (size_t)k * D_);
        float dot = 0.f;
        #pragma unroll
        for (int t = 0; t < 2; t++) {
            float4 xv = xr[lane * 2 + t];
            float4 cv = cr[lane * 2 + t];
            dot = fmaf(xv.x, cv.x, dot);
            dot = fmaf(xv.y, cv.y, dot);
            dot = fmaf(xv.z, cv.z, dot);
            dot = fmaf(xv.w, cv.w, dot);
        }
        #pragma unroll
        for (int o = 16; o > 0; o >>= 1) dot += __shfl_down_sync(0xFFFFFFFFu, dot, o);
        if (lane == 0) {
            float sc = __fadd_rn(__fadd_rn(g_A[pix], __fmul_rn(-2.0f, dot)), g_cn[k]);
            unsigned long long key =
                ((unsigned long long)float_to_ordered(sc) << 32) | (unsigned long long)k;
            atomicMin(&g_best[pix], key);
        }
    }
}

// ---------------------------------------------------------------------------
// Kernel 6: gather output (NCHW), smem-staged code rows.
// Bank-conflict fix vs R10: row stride 257 (odd) makes the output-phase reads
// rows[lane][d] conflict-free (bank = lane + d mod 32, all distinct). Staging
// uses float4 gmem loads split into scalar smem stores.
// ---------------------------------------------------------------------------
__global__ __launch_bounds__(256)
void gather_kernel(const float* __restrict__ C, float* __restrict__ out) {
    __shared__ float rows[32][257];
    __shared__ int s_k[32];
    const int tid = threadIdx.x, lane = tid & 31, wid = tid >> 5;
    const int b  = blockIdx.x >> 5;
    const int pB = (blockIdx.x & 31) * 32;

    if (tid < 32)
        s_k[tid] = (int)(unsigned int)(g_best[b * HW_ + pB + tid] & 1023u);
    __syncthreads();

    const float4* C4 = reinterpret_cast<const float4*>(C);
    #pragma unroll
    for (int i = 0; i < 8; i++) {
        int idx = i * 256 + tid;          // 0..2047
        int r = idx >> 6, c = idx & 63;
        float4 v = C4[s_k[r] * 64 + c];
        rows[r][c * 4 + 0] = v.x;
        rows[r][c * 4 + 1] = v.y;
        rows[r][c * 4 + 2] = v.z;
        rows[r][c * 4 + 3] = v.w;
    }
    __syncthreads();

    float* ob = out + (size_t)b * D_ * HW_ + pB;
    #pragma unroll
    for (int it = 0; it < 32; it++) {
        int d = it * 8 + wid;
        ob[(size_t)d * HW_ + lane] = rows[lane][d];
    }
}

// ---------------------------------------------------------------------------
// Kernel 7: loss = 1.25 * sum(per-pixel min scores) / NELM, from g_best.
// ---------------------------------------------------------------------------
__global__ __launch_bounds__(1024)
void finalize_kernel(float* __restrict__ out, int loss_idx) {
    __shared__ double red[1024];
    double s = 0.0;
    for (int i = threadIdx.x; i < NPIX; i += 1024)
        s += (double)ordered_to_float((unsigned)(g_best[i] >> 32));
    red[threadIdx.x] = s;
    __syncthreads();
    for (int o = 512; o > 0; o >>= 1) {
        if (threadIdx.x < o) red[threadIdx.x] += red[threadIdx.x + o];
        __syncthreads();
    }
    if (threadIdx.x == 0)
        out[loss_idx] = (float)(1.25 * red[0] / (double)NELM);
}

// ---------------------------------------------------------------------------
extern "C" void kernel_launch(void* const* d_in, const int* in_sizes, int n_in,
                              void* d_out, int out_size) {
    const float* X = (const float*)d_in[0];   // [64,256,32,32] f32 NCHW
    const float* C = (const float*)d_in[1];   // [1024,256] f32
    float* out = (float*)d_out;

    static const int SMEM_BYTES = 196608 + 1024;   // A + 2xB (+ align slack)
    cudaFuncSetAttribute(vq_mma_kernel,
                         cudaFuncAttributeMaxDynamicSharedMemorySize, SMEM_BYTES);

    cn_cbf_kernel<<<K_ / 32, 256>>>(C);
    a_kernel<<<NPIX / 256, 256>>>(X);
    transpose_kernel<<<dim3(HW_ / 32, D_ / 32, B_), dim3(32, 8)>>>(X);
    vq_mma_kernel<<<NPIX / 128, 512, SMEM_BYTES>>>();
    rescore_kernel<<<1024, 256>>>(C);
    gather_kernel<<<NPIX / 32, 256>>>(C, out);
    if (out_size > NELM) {
        finalize_kernel<<<1, 1024>>>(out, out_size - 1);
    }
}

// round 14
// speedup vs baseline: 1.1982x; 1.0338x over previous
#include <cuda_runtime.h>
#include <cuda_bf16.h>
#include <cstdint>

// Problem constants (fixed for this dataset)
#define B_   64
#define D_   256
#define HW_  1024            // 32*32
#define K_   1024            // num embeddings
#define NPIX (B_ * HW_)      // 65536
#define NELM (B_ * D_ * HW_) // 16777216
#define CAND_CAP 1048576
#define EPS_MARGIN 5e-3f
#define STAGE_CAP 1280       // 64-pixel tiles: ~550 expected, 2.3x headroom

// ---------------------------------------------------------------------------
// Scratch (device globals; no cudaMalloc allowed)
// ---------------------------------------------------------------------------
__device__ unsigned long long g_best[NPIX];   // packed (orderable_score<<32)|k
__device__ float g_cn[K_];                    // |c_k|^2 (exact sequential chain)
__device__ float g_A[NPIX];                   // |x_n|^2 (exact sequential chain)
__device__ float g_Xt[NPIX * D_];             // X transposed: [pix][d] fp32
__device__ __nv_bfloat16 g_Xt_bf[NPIX * D_];  // bf16 copy
__device__ __nv_bfloat16 g_Cbf[K_ * D_];      // codebook bf16
__device__ unsigned long long g_cand[CAND_CAP]; // (score_bits<<32)|(pix<<10)|k
__device__ unsigned int g_ncand;
__device__ float g_part[NPIX / 32];           // per-gather-block loss partials

__device__ __forceinline__ unsigned int float_to_ordered(float f) {
    unsigned int u = __float_as_uint(f);
    return (u & 0x80000000u) ? ~u : (u | 0x80000000u);
}
__device__ __forceinline__ float ordered_to_float(unsigned int o) {
    unsigned int u = (o & 0x80000000u) ? (o & 0x7FFFFFFFu) : ~o;
    return __uint_as_float(u);
}

__device__ __forceinline__ uint32_t smem_u32(const void* p) {
    uint32_t a;
    asm("{ .reg .u64 t; cvta.to.shared.u64 t, %1; cvt.u32.u64 %0, t; }"
        : "=r"(a) : "l"(p));
    return a;
}

// cp.async 16B (sm_80+, legal on plain sm_103 target)
__device__ __forceinline__ void cp16(uint32_t saddr, const void* g) {
    asm volatile("cp.async.cg.shared.global [%0], [%1], 16;"
                 :: "r"(saddr), "l"(g) : "memory");
}

// ldmatrix x4 (non-transposed, b16)
__device__ __forceinline__ void ldm_x4(uint32_t* r, uint32_t addr) {
    asm volatile("ldmatrix.sync.aligned.m8n8.x4.shared.b16 {%0,%1,%2,%3}, [%4];"
                 : "=r"(r[0]), "=r"(r[1]), "=r"(r[2]), "=r"(r[3]) : "r"(addr));
}

// bf16 HMMA m16n8k16, f32 accumulate (sm_80+)
__device__ __forceinline__ void mma_bf16(float* c, const uint32_t* a,
                                         uint32_t b0, uint32_t b1) {
    asm volatile(
        "mma.sync.aligned.m16n8k16.row.col.f32.bf16.bf16.f32 "
        "{%0,%1,%2,%3}, {%4,%5,%6,%7}, {%8,%9}, {%0,%1,%2,%3};"
        : "+f"(c[0]), "+f"(c[1]), "+f"(c[2]), "+f"(c[3])
        : "r"(a[0]), "r"(a[1]), "r"(a[2]), "r"(a[3]), "r"(b0), "r"(b1));
}

// ---------------------------------------------------------------------------
// Kernel 1: |c_k|^2 (exact sequential chain) + bf16 convert, coalesced.
// ---------------------------------------------------------------------------
__global__ __launch_bounds__(256)
void cn_cbf_kernel(const float* __restrict__ C) {
    __shared__ float rows[32][257];
    const int tid = threadIdx.x;
    const int kb = blockIdx.x * 32;
    if (blockIdx.x == 0 && tid == 0) g_ncand = 0;

    const float4* C4 = reinterpret_cast<const float4*>(C + (size_t)kb * D_);
    uint2* B2 = reinterpret_cast<uint2*>(g_Cbf + (size_t)kb * D_);
    #pragma unroll
    for (int i = 0; i < 8; i++) {
        int idx = i * 256 + tid;          // float4 index: 0..2047
        int r = idx >> 6, c = idx & 63;   // 64 float4 per row
        float4 v = C4[idx];
        rows[r][c * 4 + 0] = v.x;
        rows[r][c * 4 + 1] = v.y;
        rows[r][c * 4 + 2] = v.z;
        rows[r][c * 4 + 3] = v.w;
        __nv_bfloat162 h01 = __floats2bfloat162_rn(v.x, v.y);
        __nv_bfloat162 h23 = __floats2bfloat162_rn(v.z, v.w);
        uint2 pk;
        pk.x = *reinterpret_cast<unsigned int*>(&h01);
        pk.y = *reinterpret_cast<unsigned int*>(&h23);
        B2[idx] = pk;
    }
    __syncthreads();
    if (tid < 32) {
        float s = 0.f;
        #pragma unroll 8
        for (int d = 0; d < D_; d++) {
            float v = rows[tid][d];
            s = __fadd_rn(s, __fmul_rn(v, v));
        }
        g_cn[kb + tid] = s;
    }
}

// ---------------------------------------------------------------------------
// Kernel 2: |x_p|^2 (exact sequential chain). 256x256, coalesced.
// ---------------------------------------------------------------------------
__global__ __launch_bounds__(256)
void a_kernel(const float* __restrict__ X) {
    const int pix = blockIdx.x * 256 + threadIdx.x;
    const int b = pix >> 10, p = pix & 1023;
    const float* Xb = X + (size_t)b * D_ * HW_ + p;
    float s = 0.f;
    #pragma unroll 8
    for (int d = 0; d < D_; d++) {
        float v = Xb[(size_t)d * HW_];
        s = __fadd_rn(s, __fmul_rn(v, v));
    }
    g_A[pix] = s;
}

// ---------------------------------------------------------------------------
// Kernel 3: transpose X NCHW [b][d][p] -> pixel-major [pix][d], f32+bf16
// ---------------------------------------------------------------------------
__global__ __launch_bounds__(256)
void transpose_kernel(const float* __restrict__ X) {
    __shared__ float t[32][33];
    const int b  = blockIdx.z;
    const int dB = blockIdx.y * 32;
    const int pB = blockIdx.x * 32;
    const int tx = threadIdx.x;       // 0..31
    const int ty = threadIdx.y;       // 0..7

    const float* src = X + ((size_t)b * D_ + dB) * HW_ + pB;
    #pragma unroll
    for (int i = 0; i < 32; i += 8)
        t[ty + i][tx] = src[(size_t)(ty + i) * HW_ + tx];
    __syncthreads();

    const size_t obase = ((size_t)(b * HW_ + pB)) * D_ + dB;
    #pragma unroll
    for (int i = 0; i < 32; i += 8) {
        int row = ty + i;
        float v = t[tx][row];
        g_Xt[obase + (size_t)row * D_ + tx] = v;
        g_Xt_bf[obase + (size_t)row * D_ + tx] = __float2bfloat16(v);
    }
}

// ---------------------------------------------------------------------------
// Kernel 4: persistent-A bf16 HMMA GEMM, 64 pixels x ALL 1024 codes per CTA.
// 256 threads / 8 warps, warp tile 32x16, 2-stage register fragment pipeline.
// Small CTA (A 32KB + 2x32KB B + ~15KB static = 112KB) -> 2 CTAs/SM: two
// independent barrier groups hide each other's kt-barrier / emission stalls.
// Per-thread divergent emission; singles write g_best with full score
// A + (cn-2dot); multis go to g_cand for the separate exact-rescore kernel.
// ---------------------------------------------------------------------------
__global__ __launch_bounds__(256, 2)
void vq_mma_kernel() {
    extern __shared__ char dsm_raw[];
    __shared__ float s_cn[K_];
    __shared__ float s_A[64];
    __shared__ unsigned int s_min[64];
    __shared__ unsigned int s_pcount[64];
    __shared__ unsigned long long stage[STAGE_CAP];
    __shared__ unsigned int s_cnt;

    const int tid = threadIdx.x, lane = tid & 31, wid = tid >> 5;
    const int pt = blockIdx.x;   // 0..1023 pixel tiles (64 pixels each)

    const uint32_t s0 = smem_u32(dsm_raw);
    const uint32_t base = (s0 + 1023) & ~1023u;
    const uint32_t sA = base;                       // 32KB: 64 px rows
    const uint32_t sB0 = base + 32768, sB1 = base + 65536;  // 2x 32KB B

    #pragma unroll
    for (int i = 0; i < 4; i++) s_cn[tid + i * 256] = g_cn[tid + i * 256];
    if (tid < 64) {
        s_min[tid] = 0xFFFFFFFFu;
        s_pcount[tid] = 0u;
        s_A[tid] = g_A[pt * 64 + tid];
        g_best[pt * 64 + tid] = 0xFFFFFFFFFFFFFFFFull;
    }
    if (tid == 0) s_cnt = 0;

    // Stage A (once, 2048 chunks) + B tile 0 (2048 chunks)
    const __nv_bfloat16* gA = g_Xt_bf + (size_t)pt * 64 * D_;
    #pragma unroll
    for (int i = 0; i < 8; i++) {
        int v = i * 256 + tid;             // 0..2047 16B chunks
        int r = v >> 5, c = v & 31;
        uint32_t off = (uint32_t)(r * 512) + (((uint32_t)c * 16) ^ ((uint32_t)(r & 7) << 4));
        cp16(sA + off, gA + (size_t)v * 8);
        cp16(sB0 + off, g_Cbf + (size_t)v * 8);
    }
    asm volatile("cp.async.commit_group;");

    // Warp tiling: 2 (m) x 4 (n); warp tile 32 px x 16 codes
    const int wm = (wid & 1) * 32;
    const int wn = (wid >> 1) * 16;
    const int a_row = wm + (lane & 15);
    const uint32_t a_swz = (uint32_t)((a_row & 7) << 4);
    const int a_kb = (lane >> 4) * 16;
    const int b_row = wn + ((lane & 7) | ((lane & 16) >> 1));
    const uint32_t b_swz = (uint32_t)((b_row & 7) << 4);
    const int b_kb = ((lane >> 3) & 1) * 16;

    const int r0b = wm + (lane >> 2);          // score row base (mi adds 16)
    const int c0b = wn + (lane & 3) * 2;       // score col base (n8 adds 8)

    const uint32_t aAddr0 = sA + (uint32_t)a_row * 512;
    const uint32_t aAddr1 = sA + (uint32_t)(a_row + 16) * 512;

    for (int kt = 0; kt < 16; kt++) {
        const uint32_t sBc = (kt & 1) ? sB1 : sB0;
        const uint32_t sBn = (kt & 1) ? sB0 : sB1;

        asm volatile("cp.async.wait_group 0;" ::: "memory");
        __syncthreads();

        // Prefetch next B tile (64 codes = 2048 chunks) into alternate buffer
        if (kt + 1 < 16) {
            const __nv_bfloat16* gBn = g_Cbf + (size_t)(kt + 1) * 64 * D_;
            #pragma unroll
            for (int i = 0; i < 8; i++) {
                int v = i * 256 + tid;
                int r = v >> 5, c = v & 31;
                uint32_t off = (uint32_t)(r * 512) +
                               (((uint32_t)c * 16) ^ ((uint32_t)(r & 7) << 4));
                cp16(sBn + off, gBn + (size_t)v * 8);
            }
            asm volatile("cp.async.commit_group;");
        }

        const uint32_t bAddr = sBc + (uint32_t)b_row * 512;

        float acc[2][2][4];
        #pragma unroll
        for (int mi = 0; mi < 2; mi++)
            #pragma unroll
            for (int n8 = 0; n8 < 2; n8++)
                #pragma unroll
                for (int e = 0; e < 4; e++) acc[mi][n8][e] = 0.f;

        // 2-stage register fragment pipeline over ks
        uint32_t afb[2][2][4], bfb[2][4];
        {
            uint32_t ka = (uint32_t)a_kb ^ a_swz;
            uint32_t kb = (uint32_t)b_kb ^ b_swz;
            ldm_x4(afb[0][0], aAddr0 + ka);
            ldm_x4(afb[0][1], aAddr1 + ka);
            ldm_x4(bfb[0], bAddr + kb);
        }
        #pragma unroll
        for (int ks = 0; ks < 16; ks++) {
            const int cur = ks & 1, nxt = cur ^ 1;
            if (ks < 15) {
                uint32_t ka = ((uint32_t)((ks + 1) * 32 + a_kb)) ^ a_swz;
                uint32_t kb = ((uint32_t)((ks + 1) * 32 + b_kb)) ^ b_swz;
                ldm_x4(afb[nxt][0], aAddr0 + ka);
                ldm_x4(afb[nxt][1], aAddr1 + ka);
                ldm_x4(bfb[nxt], bAddr + kb);
            }
            #pragma unroll
            for (int mi = 0; mi < 2; mi++)
                #pragma unroll
                for (int n8 = 0; n8 < 2; n8++)
                    mma_bf16(acc[mi][n8], afb[cur][mi],
                             bfb[cur][n8 * 2], bfb[cur][n8 * 2 + 1]);
        }

        // Scores IN PLACE: acc <- cn[k] - 2*acc. Update per-pixel running min.
        #pragma unroll
        for (int mi = 0; mi < 2; mi++) {
            float m0 = 3.4e38f, m1 = 3.4e38f;
            #pragma unroll
            for (int n8 = 0; n8 < 2; n8++) {
                int c0 = c0b + n8 * 8;
                float cn0 = s_cn[kt * 64 + c0], cn1 = s_cn[kt * 64 + c0 + 1];
                acc[mi][n8][0] = fmaf(-2.f, acc[mi][n8][0], cn0);
                acc[mi][n8][1] = fmaf(-2.f, acc[mi][n8][1], cn1);
                acc[mi][n8][2] = fmaf(-2.f, acc[mi][n8][2], cn0);
                acc[mi][n8][3] = fmaf(-2.f, acc[mi][n8][3], cn1);
                m0 = fminf(m0, fminf(acc[mi][n8][0], acc[mi][n8][1]));
                m1 = fminf(m1, fminf(acc[mi][n8][2], acc[mi][n8][3]));
            }
            m0 = fminf(m0, __shfl_xor_sync(0xFFFFFFFFu, m0, 1));
            m0 = fminf(m0, __shfl_xor_sync(0xFFFFFFFFu, m0, 2));
            m1 = fminf(m1, __shfl_xor_sync(0xFFFFFFFFu, m1, 1));
            m1 = fminf(m1, __shfl_xor_sync(0xFFFFFFFFu, m1, 2));
            if ((lane & 3) == 0) {
                atomicMin(&s_min[r0b + mi * 16],     float_to_ordered(m0));
                atomicMin(&s_min[r0b + mi * 16 + 8], float_to_ordered(m1));
            }
        }
        // NO syncthreads: stale (larger) min still yields a candidate superset.

        // Emit candidates vs running min (per-thread, rare-divergent)
        const unsigned pixb = (unsigned)(pt * 64);
        #pragma unroll
        for (int mi = 0; mi < 2; mi++) {
            int r0 = r0b + mi * 16;
            float thr0 = ordered_to_float(s_min[r0]) + EPS_MARGIN;
            float thr1 = ordered_to_float(s_min[r0 + 8]) + EPS_MARGIN;
            #pragma unroll
            for (int n8 = 0; n8 < 2; n8++) {
                int c0 = c0b + n8 * 8;
                #pragma unroll
                for (int e = 0; e < 4; e++) {
                    float v = acc[mi][n8][e];
                    float thr = (e < 2) ? thr0 : thr1;
                    if (v <= thr) {
                        unsigned row = (unsigned)(r0 + ((e < 2) ? 0 : 8));
                        unsigned k = (unsigned)(kt * 64 + c0 + (e & 1));
                        unsigned long long entry =
                            ((unsigned long long)__float_as_uint(v) << 32) |
                            ((unsigned long long)(pixb + row) << 10) | k;
                        unsigned slot = atomicAdd(&s_cnt, 1u);
                        if (slot < STAGE_CAP) stage[slot] = entry;
                        else {
                            unsigned gs = atomicAdd(&g_ncand, 1u);
                            if (gs < CAND_CAP) g_cand[gs] = entry;
                        }
                    }
                }
            }
        }
    }
    __syncthreads();

    // Final flush, pass 1: count final-filtered candidates per pixel
    const unsigned total = min(s_cnt, (unsigned)STAGE_CAP);
    const bool oflow = (s_cnt > (unsigned)STAGE_CAP);
    for (unsigned i = tid; i < total; i += 256) {
        unsigned long long e = stage[i];
        float v = __uint_as_float((unsigned)(e >> 32));
        unsigned row = ((unsigned)e >> 10) & 63u;
        if (v <= ordered_to_float(s_min[row]) + EPS_MARGIN)
            atomicAdd(&s_pcount[row], 1u);
    }
    __syncthreads();

    // Pass 2: singles -> direct g_best write (full score A + filter score);
    //         multis -> g_cand for exact rescoring.
    const unsigned rounded = (total + 255u) & ~255u;
    for (unsigned i = tid; i < rounded; i += 256) {
        bool pred = false;
        unsigned long long e = 0;
        if (i < total) {
            e = stage[i];
            float v = __uint_as_float((unsigned)(e >> 32));
            unsigned low = (unsigned)e;
            unsigned row = (low >> 10) & 63u;
            if (v <= ordered_to_float(s_min[row]) + EPS_MARGIN) {
                if (s_pcount[row] == 1u && !oflow) {
                    unsigned pix = low >> 10, k = low & 1023u;
                    float full = __fadd_rn(s_A[row], v);   // A + (cn - 2dot)
                    unsigned long long key =
                        ((unsigned long long)float_to_ordered(full) << 32) |
                        (unsigned long long)k;
                    atomicMin(&g_best[pix], key);
                } else {
                    pred = true;
                }
            }
        }
        unsigned mask = __ballot_sync(0xFFFFFFFFu, pred);
        if (mask) {
            int leader = __ffs(mask) - 1;
            unsigned bidx = 0;
            if (lane == leader) bidx = atomicAdd(&g_ncand, (unsigned)__popc(mask));
            bidx = __shfl_sync(0xFFFFFFFFu, bidx, leader);
            if (pred) {
                unsigned dst = bidx + __popc(mask & ((1u << lane) - 1u));
                if (dst < CAND_CAP) g_cand[dst] = e;
            }
        }
    }
}

// ---------------------------------------------------------------------------
// Kernel 5: exact fp32 rescore of multi-candidate entries (one warp each).
// score = fl(fl(A - 2*dot) + cn)  — the Round-2-validated rounding chain.
// ---------------------------------------------------------------------------
__global__ __launch_bounds__(256)
void rescore_kernel(const float* __restrict__ C) {
    const unsigned int count = min(g_ncand, (unsigned)CAND_CAP);
    const int lane = threadIdx.x & 31;
    const unsigned gw = (blockIdx.x * blockDim.x + threadIdx.x) >> 5;
    const unsigned nw = (gridDim.x * blockDim.x) >> 5;

    for (unsigned i = gw; i < count; i += nw) {
        unsigned long long e = g_cand[i];
        unsigned low = (unsigned)e;
        unsigned pix = low >> 10, k = low & 1023u;

        const float4* xr = reinterpret_cast<const float4*>(g_Xt + (size_t)pix * D_);
        const float4* cr = reinterpret_cast<const float4*>(C + (size_t)k * D_);
        float dot = 0.f;
        #pragma unroll
        for (int t = 0; t < 2; t++) {
            float4 xv = xr[lane * 2 + t];
            float4 cv = cr[lane * 2 + t];
            dot = fmaf(xv.x, cv.x, dot);
            dot = fmaf(xv.y, cv.y, dot);
            dot = fmaf(xv.z, cv.z, dot);
            dot = fmaf(xv.w, cv.w, dot);
        }
        #pragma unroll
        for (int o = 16; o > 0; o >>= 1) dot += __shfl_down_sync(0xFFFFFFFFu, dot, o);
        if (lane == 0) {
            float sc = __fadd_rn(__fadd_rn(g_A[pix], __fmul_rn(-2.0f, dot)), g_cn[k]);
            unsigned long long key =
                ((unsigned long long)float_to_ordered(sc) << 32) | (unsigned long long)k;
            atomicMin(&g_best[pix], key);
        }
    }
}

// ---------------------------------------------------------------------------
// Kernel 6: gather output (NCHW), smem-staged code rows (stride-257,
// conflict-free reads) + per-block loss partial from g_best keys.
// ---------------------------------------------------------------------------
__global__ __launch_bounds__(256)
void gather_kernel(const float* __restrict__ C, float* __restrict__ out) {
    __shared__ float rows[32][257];
    __shared__ int s_k[32];
    const int tid = threadIdx.x, lane = tid & 31, wid = tid >> 5;
    const int b  = blockIdx.x >> 5;
    const int pB = (blockIdx.x & 31) * 32;

    if (tid < 32) {
        unsigned long long key = g_best[b * HW_ + pB + tid];
        s_k[tid] = (int)(unsigned int)(key & 1023u);
        // loss partial: sum of the 32 per-pixel min scores
        float sc = ordered_to_float((unsigned)(key >> 32));
        #pragma unroll
        for (int o = 16; o > 0; o >>= 1) sc += __shfl_down_sync(0xFFFFFFFFu, sc, o);
        if (tid == 0) g_part[blockIdx.x] = sc;
    }
    __syncthreads();

    const float4* C4 = reinterpret_cast<const float4*>(C);
    #pragma unroll
    for (int i = 0; i < 8; i++) {
        int idx = i * 256 + tid;          // 0..2047
        int r = idx >> 6, c = idx & 63;
        float4 v = C4[s_k[r] * 64 + c];
        rows[r][c * 4 + 0] = v.x;
        rows[r][c * 4 + 1] = v.y;
        rows[r][c * 4 + 2] = v.z;
        rows[r][c * 4 + 3] = v.w;
    }
    __syncthreads();

    float* ob = out + (size_t)b * D_ * HW_ + pB;
    #pragma unroll
    for (int it = 0; it < 32; it++) {
        int d = it * 8 + wid;
        ob[(size_t)d * HW_ + lane] = rows[lane][d];
    }
}

// ---------------------------------------------------------------------------
// Kernel 7: loss = 1.25 * sum(g_part) / NELM  (2048 partials, deterministic).
// ---------------------------------------------------------------------------
__global__ __launch_bounds__(1024)
void finalize_kernel(float* __restrict__ out, int loss_idx) {
    __shared__ double red[1024];
    double s = 0.0;
    for (int i = threadIdx.x; i < NPIX / 32; i += 1024)
        s += (double)g_part[i];
    red[threadIdx.x] = s;
    __syncthreads();
    for (int o = 512; o > 0; o >>= 1) {
        if (threadIdx.x < o) red[threadIdx.x] += red[threadIdx.x + o];
        __syncthreads();
    }
    if (threadIdx.x == 0)
        out[loss_idx] = (float)(1.25 * red[0] / (double)NELM);
}

// ---------------------------------------------------------------------------
extern "C" void kernel_launch(void* const* d_in, const int* in_sizes, int n_in,
                              void* d_out, int out_size) {
    const float* X = (const float*)d_in[0];   // [64,256,32,32] f32 NCHW
    const float* C = (const float*)d_in[1];   // [1024,256] f32
    float* out = (float*)d_out;

    static const int SMEM_BYTES = 98304 + 1024;   // A(32K) + 2xB(32K) + slack
    cudaFuncSetAttribute(vq_mma_kernel,
                         cudaFuncAttributeMaxDynamicSharedMemorySize, SMEM_BYTES);

    cn_cbf_kernel<<<K_ / 32, 256>>>(C);
    a_kernel<<<NPIX / 256, 256>>>(X);
    transpose_kernel<<<dim3(HW_ / 32, D_ / 32, B_), dim3(32, 8)>>>(X);
    vq_mma_kernel<<<NPIX / 64, 256, SMEM_BYTES>>>();
    rescore_kernel<<<512, 256>>>(C);
    gather_kernel<<<NPIX / 32, 256>>>(C, out);
    if (out_size > NELM) {
        finalize_kernel<<<1, 1024>>>(out, out_size - 1);
    }
}

// round 15
// speedup vs baseline: 1.2808x; 1.0689x over previous
#include <cuda_runtime.h>
#include <cuda_bf16.h>
#include <cstdint>

// Problem constants (fixed for this dataset)
#define B_   64
#define D_   256
#define HW_  1024            // 32*32
#define K_   1024            // num embeddings
#define NPIX (B_ * HW_)      // 65536
#define NELM (B_ * D_ * HW_) // 16777216
#define CAND_CAP 1048576
#define EPS_MARGIN 5e-3f
#define STAGE_CAP 2816

// ---------------------------------------------------------------------------
// Scratch (device globals; no cudaMalloc allowed)
// ---------------------------------------------------------------------------
__device__ unsigned long long g_best[NPIX];   // packed (orderable_score<<32)|k
__device__ float g_cn[K_];                    // |c_k|^2 (exact sequential chain)
__device__ float g_A[NPIX];                   // |x_n|^2 (exact sequential chain)
__device__ float g_Xt[NPIX * D_];             // X transposed: [pix][d] fp32
__device__ __nv_bfloat16 g_Xt_bf[NPIX * D_];  // bf16 copy
__device__ __nv_bfloat16 g_Cbf[K_ * D_];      // codebook bf16
__device__ unsigned long long g_cand[CAND_CAP]; // (score_bits<<32)|(pix<<10)|k
__device__ unsigned int g_ncand;
__device__ float g_part[NPIX / 32];           // per-gather-block loss partials

__device__ __forceinline__ unsigned int float_to_ordered(float f) {
    unsigned int u = __float_as_uint(f);
    return (u & 0x80000000u) ? ~u : (u | 0x80000000u);
}
__device__ __forceinline__ float ordered_to_float(unsigned int o) {
    unsigned int u = (o & 0x80000000u) ? (o & 0x7FFFFFFFu) : ~o;
    return __uint_as_float(u);
}

__device__ __forceinline__ uint32_t smem_u32(const void* p) {
    uint32_t a;
    asm("{ .reg .u64 t; cvta.to.shared.u64 t, %1; cvt.u32.u64 %0, t; }"
        : "=r"(a) : "l"(p));
    return a;
}

// cp.async 16B (sm_80+, legal on plain sm_103 target)
__device__ __forceinline__ void cp16(uint32_t saddr, const void* g) {
    asm volatile("cp.async.cg.shared.global [%0], [%1], 16;"
                 :: "r"(saddr), "l"(g) : "memory");
}

// ldmatrix x4 (non-transposed, b16)
__device__ __forceinline__ void ldm_x4(uint32_t* r, uint32_t addr) {
    asm volatile("ldmatrix.sync.aligned.m8n8.x4.shared.b16 {%0,%1,%2,%3}, [%4];"
                 : "=r"(r[0]), "=r"(r[1]), "=r"(r[2]), "=r"(r[3]) : "r"(addr));
}

// bf16 HMMA m16n8k16, f32 accumulate (sm_80+)
__device__ __forceinline__ void mma_bf16(float* c, const uint32_t* a,
                                         uint32_t b0, uint32_t b1) {
    asm volatile(
        "mma.sync.aligned.m16n8k16.row.col.f32.bf16.bf16.f32 "
        "{%0,%1,%2,%3}, {%4,%5,%6,%7}, {%8,%9}, {%0,%1,%2,%3};"
        : "+f"(c[0]), "+f"(c[1]), "+f"(c[2]), "+f"(c[3])
        : "r"(a[0]), "r"(a[1]), "r"(a[2]), "r"(a[3]), "r"(b0), "r"(b1));
}

// ---------------------------------------------------------------------------
// Kernel 1: |c_k|^2 (exact sequential chain) + bf16 convert, coalesced.
// ---------------------------------------------------------------------------
__global__ __launch_bounds__(256)
void cn_cbf_kernel(const float* __restrict__ C) {
    __shared__ float rows[32][257];
    const int tid = threadIdx.x;
    const int kb = blockIdx.x * 32;
    if (blockIdx.x == 0 && tid == 0) g_ncand = 0;

    const float4* C4 = reinterpret_cast<const float4*>(C + (size_t)kb * D_);
    uint2* B2 = reinterpret_cast<uint2*>(g_Cbf + (size_t)kb * D_);
    #pragma unroll
    for (int i = 0; i < 8; i++) {
        int idx = i * 256 + tid;          // float4 index: 0..2047
        int r = idx >> 6, c = idx & 63;   // 64 float4 per row
        float4 v = C4[idx];
        rows[r][c * 4 + 0] = v.x;
        rows[r][c * 4 + 1] = v.y;
        rows[r][c * 4 + 2] = v.z;
        rows[r][c * 4 + 3] = v.w;
        __nv_bfloat162 h01 = __floats2bfloat162_rn(v.x, v.y);
        __nv_bfloat162 h23 = __floats2bfloat162_rn(v.z, v.w);
        uint2 pk;
        pk.x = *reinterpret_cast<unsigned int*>(&h01);
        pk.y = *reinterpret_cast<unsigned int*>(&h23);
        B2[idx] = pk;
    }
    __syncthreads();
    if (tid < 32) {
        float s = 0.f;
        #pragma unroll 8
        for (int d = 0; d < D_; d++) {
            float v = rows[tid][d];
            s = __fadd_rn(s, __fmul_rn(v, v));
        }
        g_cn[kb + tid] = s;
    }
}

// ---------------------------------------------------------------------------
// Kernel 2: |x_p|^2 (exact sequential chain). 256x256, coalesced.
// ---------------------------------------------------------------------------
__global__ __launch_bounds__(256)
void a_kernel(const float* __restrict__ X) {
    const int pix = blockIdx.x * 256 + threadIdx.x;
    const int b = pix >> 10, p = pix & 1023;
    const float* Xb = X + (size_t)b * D_ * HW_ + p;
    float s = 0.f;
    #pragma unroll 8
    for (int d = 0; d < D_; d++) {
        float v = Xb[(size_t)d * HW_];
        s = __fadd_rn(s, __fmul_rn(v, v));
    }
    g_A[pix] = s;
}

// ---------------------------------------------------------------------------
// Kernel 3: transpose X NCHW [b][d][p] -> pixel-major [pix][d], f32+bf16
// ---------------------------------------------------------------------------
__global__ __launch_bounds__(256)
void transpose_kernel(const float* __restrict__ X) {
    __shared__ float t[32][33];
    const int b  = blockIdx.z;
    const int dB = blockIdx.y * 32;
    const int pB = blockIdx.x * 32;
    const int tx = threadIdx.x;       // 0..31
    const int ty = threadIdx.y;       // 0..7

    const float* src = X + ((size_t)b * D_ + dB) * HW_ + pB;
    #pragma unroll
    for (int i = 0; i < 32; i += 8)
        t[ty + i][tx] = src[(size_t)(ty + i) * HW_ + tx];
    __syncthreads();

    const size_t obase = ((size_t)(b * HW_ + pB)) * D_ + dB;
    #pragma unroll
    for (int i = 0; i < 32; i += 8) {
        int row = ty + i;
        float v = t[tx][row];
        g_Xt[obase + (size_t)row * D_ + tx] = v;
        g_Xt_bf[obase + (size_t)row * D_ + tx] = __float2bfloat16(v);
    }
}

// ---------------------------------------------------------------------------
// Kernel 4: persistent-A bf16 HMMA GEMM, 128 pixels x ALL 1024 codes per CTA.
// 512 threads / 16 warps, 32x32 warp tile, 2-stage register fragment pipeline.
// (R13-validated 156.9us configuration — do not touch.)
// ---------------------------------------------------------------------------
__global__ __launch_bounds__(512, 1)
void vq_mma_kernel() {
    extern __shared__ char dsm_raw[];
    __shared__ float s_cn[K_];
    __shared__ float s_A[128];
    __shared__ unsigned int s_min[128];
    __shared__ unsigned int s_pcount[128];
    __shared__ unsigned long long stage[STAGE_CAP];
    __shared__ unsigned int s_cnt;

    const int tid = threadIdx.x, lane = tid & 31, wid = tid >> 5;
    const int pt = blockIdx.x;   // 0..511 pixel tiles (128 pixels each)

    const uint32_t s0 = smem_u32(dsm_raw);
    const uint32_t base = (s0 + 1023) & ~1023u;
    const uint32_t sA = base;
    const uint32_t sB0 = base + 65536, sB1 = base + 131072;

    #pragma unroll
    for (int i = 0; i < 2; i++) s_cn[tid + i * 512] = g_cn[tid + i * 512];
    if (tid < 128) {
        s_min[tid] = 0xFFFFFFFFu;
        s_pcount[tid] = 0u;
        s_A[tid] = g_A[pt * 128 + tid];
        g_best[pt * 128 + tid] = 0xFFFFFFFFFFFFFFFFull;
    }
    if (tid == 0) s_cnt = 0;

    // Stage A (once) + B tile 0
    const __nv_bfloat16* gA = g_Xt_bf + (size_t)pt * 128 * D_;
    #pragma unroll
    for (int i = 0; i < 8; i++) {
        int v = i * 512 + tid;             // 0..4095 16B chunks
        int r = v >> 5, c = v & 31;
        uint32_t off = (uint32_t)(r * 512) + (((uint32_t)c * 16) ^ ((uint32_t)(r & 7) << 4));
        cp16(sA + off, gA + (size_t)v * 8);
        cp16(sB0 + off, g_Cbf + (size_t)v * 8);
    }
    asm volatile("cp.async.commit_group;");

    // Warp tiling: 4 (m) x 4 (n), 32x32 per warp
    const int wm = (wid & 3) * 32;
    const int wn = (wid >> 2) * 32;
    const int a_row = wm + (lane & 15);
    const uint32_t a_swz = (uint32_t)((a_row & 7) << 4);
    const int a_kb = (lane >> 4) * 16;
    const int b_row = wn + ((lane & 7) | ((lane & 16) >> 1));
    const uint32_t b_swz = (uint32_t)((b_row & 7) << 4);
    const int b_kb = ((lane >> 3) & 1) * 16;

    const int r0b = wm + (lane >> 2);          // score row base (mi adds 16)
    const int c0b = wn + (lane & 3) * 2;       // score col base (nt adds 8)

    const uint32_t aAddr0 = sA + (uint32_t)a_row * 512;
    const uint32_t aAddr1 = sA + (uint32_t)(a_row + 16) * 512;

    for (int kt = 0; kt < 8; kt++) {
        const uint32_t sBc = (kt & 1) ? sB1 : sB0;
        const uint32_t sBn = (kt & 1) ? sB0 : sB1;

        asm volatile("cp.async.wait_group 0;" ::: "memory");
        __syncthreads();

        // Prefetch next B tile into the alternate buffer
        if (kt + 1 < 8) {
            const __nv_bfloat16* gBn = g_Cbf + (size_t)(kt + 1) * 128 * D_;
            #pragma unroll
            for (int i = 0; i < 8; i++) {
                int v = i * 512 + tid;
                int r = v >> 5, c = v & 31;
                uint32_t off = (uint32_t)(r * 512) +
                               (((uint32_t)c * 16) ^ ((uint32_t)(r & 7) << 4));
                cp16(sBn + off, gBn + (size_t)v * 8);
            }
            asm volatile("cp.async.commit_group;");
        }

        const uint32_t bAddr0 = sBc + (uint32_t)b_row * 512;
        const uint32_t bAddr1 = sBc + (uint32_t)(b_row + 16) * 512;

        float acc[2][4][4];
        #pragma unroll
        for (int mi = 0; mi < 2; mi++)
            #pragma unroll
            for (int nt = 0; nt < 4; nt++)
                #pragma unroll
                for (int e = 0; e < 4; e++) acc[mi][nt][e] = 0.f;

        // 2-stage register fragment pipeline over ks
        uint32_t afb[2][2][4], bfb[2][2][4];
        {
            uint32_t ka = (uint32_t)a_kb ^ a_swz;
            uint32_t kb = (uint32_t)b_kb ^ b_swz;
            ldm_x4(afb[0][0], aAddr0 + ka);
            ldm_x4(afb[0][1], aAddr1 + ka);
            ldm_x4(bfb[0][0], bAddr0 + kb);
            ldm_x4(bfb[0][1], bAddr1 + kb);
        }
        #pragma unroll
        for (int ks = 0; ks < 16; ks++) {
            const int cur = ks & 1, nxt = cur ^ 1;
            if (ks < 15) {
                uint32_t ka = ((uint32_t)((ks + 1) * 32 + a_kb)) ^ a_swz;
                uint32_t kb = ((uint32_t)((ks + 1) * 32 + b_kb)) ^ b_swz;
                ldm_x4(afb[nxt][0], aAddr0 + ka);
                ldm_x4(afb[nxt][1], aAddr1 + ka);
                ldm_x4(bfb[nxt][0], bAddr0 + kb);
                ldm_x4(bfb[nxt][1], bAddr1 + kb);
            }
            #pragma unroll
            for (int mi = 0; mi < 2; mi++)
                #pragma unroll
                for (int nt = 0; nt < 4; nt++)
                    mma_bf16(acc[mi][nt], afb[cur][mi],
                             bfb[cur][nt >> 1][(nt & 1) * 2],
                             bfb[cur][nt >> 1][(nt & 1) * 2 + 1]);
        }

        // Scores IN PLACE: acc <- cn[k] - 2*acc. Update per-pixel running min.
        #pragma unroll
        for (int mi = 0; mi < 2; mi++) {
            float m0 = 3.4e38f, m1 = 3.4e38f;
            #pragma unroll
            for (int nt = 0; nt < 4; nt++) {
                int c0 = c0b + nt * 8;
                float cn0 = s_cn[kt * 128 + c0], cn1 = s_cn[kt * 128 + c0 + 1];
                acc[mi][nt][0] = fmaf(-2.f, acc[mi][nt][0], cn0);
                acc[mi][nt][1] = fmaf(-2.f, acc[mi][nt][1], cn1);
                acc[mi][nt][2] = fmaf(-2.f, acc[mi][nt][2], cn0);
                acc[mi][nt][3] = fmaf(-2.f, acc[mi][nt][3], cn1);
                m0 = fminf(m0, fminf(acc[mi][nt][0], acc[mi][nt][1]));
                m1 = fminf(m1, fminf(acc[mi][nt][2], acc[mi][nt][3]));
            }
            m0 = fminf(m0, __shfl_xor_sync(0xFFFFFFFFu, m0, 1));
            m0 = fminf(m0, __shfl_xor_sync(0xFFFFFFFFu, m0, 2));
            m1 = fminf(m1, __shfl_xor_sync(0xFFFFFFFFu, m1, 1));
            m1 = fminf(m1, __shfl_xor_sync(0xFFFFFFFFu, m1, 2));
            if ((lane & 3) == 0) {
                atomicMin(&s_min[r0b + mi * 16],     float_to_ordered(m0));
                atomicMin(&s_min[r0b + mi * 16 + 8], float_to_ordered(m1));
            }
        }
        // NO syncthreads: stale (larger) min still yields a candidate superset.

        // Emit candidates vs running min (per-thread, rare-divergent)
        const unsigned pixb = (unsigned)(pt * 128);
        #pragma unroll
        for (int mi = 0; mi < 2; mi++) {
            int r0 = r0b + mi * 16;
            float thr0 = ordered_to_float(s_min[r0]) + EPS_MARGIN;
            float thr1 = ordered_to_float(s_min[r0 + 8]) + EPS_MARGIN;
            #pragma unroll
            for (int nt = 0; nt < 4; nt++) {
                int c0 = c0b + nt * 8;
                #pragma unroll
                for (int e = 0; e < 4; e++) {
                    float v = acc[mi][nt][e];
                    float thr = (e < 2) ? thr0 : thr1;
                    if (v <= thr) {
                        unsigned row = (unsigned)(r0 + ((e < 2) ? 0 : 8));
                        unsigned k = (unsigned)(kt * 128 + c0 + (e & 1));
                        unsigned long long entry =
                            ((unsigned long long)__float_as_uint(v) << 32) |
                            ((unsigned long long)(pixb + row) << 10) | k;
                        unsigned slot = atomicAdd(&s_cnt, 1u);
                        if (slot < STAGE_CAP) stage[slot] = entry;
                        else {
                            unsigned gs = atomicAdd(&g_ncand, 1u);
                            if (gs < CAND_CAP) g_cand[gs] = entry;
                        }
                    }
                }
            }
        }
    }
    __syncthreads();

    // Final flush, pass 1: count final-filtered candidates per pixel
    const unsigned total = min(s_cnt, (unsigned)STAGE_CAP);
    const bool oflow = (s_cnt > (unsigned)STAGE_CAP);
    for (unsigned i = tid; i < total; i += 512) {
        unsigned long long e = stage[i];
        float v = __uint_as_float((unsigned)(e >> 32));
        unsigned row = ((unsigned)e >> 10) & 127u;
        if (v <= ordered_to_float(s_min[row]) + EPS_MARGIN)
            atomicAdd(&s_pcount[row], 1u);
    }
    __syncthreads();

    // Pass 2: singles -> direct g_best write (full score A + filter score);
    //         multis -> g_cand for exact rescoring.
    const unsigned rounded = (total + 511u) & ~511u;
    for (unsigned i = tid; i < rounded; i += 512) {
        bool pred = false;
        unsigned long long e = 0;
        if (i < total) {
            e = stage[i];
            float v = __uint_as_float((unsigned)(e >> 32));
            unsigned low = (unsigned)e;
            unsigned row = (low >> 10) & 127u;
            if (v <= ordered_to_float(s_min[row]) + EPS_MARGIN) {
                if (s_pcount[row] == 1u && !oflow) {
                    unsigned pix = low >> 10, k = low & 1023u;
                    float full = __fadd_rn(s_A[row], v);   // A + (cn - 2dot)
                    unsigned long long key =
                        ((unsigned long long)float_to_ordered(full) << 32) |
                        (unsigned long long)k;
                    atomicMin(&g_best[pix], key);
                } else {
                    pred = true;
                }
            }
        }
        unsigned mask = __ballot_sync(0xFFFFFFFFu, pred);
        if (mask) {
            int leader = __ffs(mask) - 1;
            unsigned bidx = 0;
            if (lane == leader) bidx = atomicAdd(&g_ncand, (unsigned)__popc(mask));
            bidx = __shfl_sync(0xFFFFFFFFu, bidx, leader);
            if (pred) {
                unsigned dst = bidx + __popc(mask & ((1u << lane) - 1u));
                if (dst < CAND_CAP) g_cand[dst] = e;
            }
        }
    }
}

// ---------------------------------------------------------------------------
// Kernel 5: exact fp32 rescore of multi-candidate entries (one warp each).
// score = fl(fl(A - 2*dot) + cn)  — the Round-2-validated rounding chain.
// ---------------------------------------------------------------------------
__global__ __launch_bounds__(256)
void rescore_kernel(const float* __restrict__ C) {
    const unsigned int count = min(g_ncand, (unsigned)CAND_CAP);
    const int lane = threadIdx.x & 31;
    const unsigned gw = (blockIdx.x * blockDim.x + threadIdx.x) >> 5;
    const unsigned nw = (gridDim.x * blockDim.x) >> 5;

    for (unsigned i = gw; i < count; i += nw) {
        unsigned long long e = g_cand[i];
        unsigned low = (unsigned)e;
        unsigned pix = low >> 10, k = low & 1023u;

        const float4* xr = reinterpret_cast<const float4*>(g_Xt + (size_t)pix * D_);
        const float4* cr = reinterpret_cast<const float4*>(C + (size_t)k * D_);
        float dot = 0.f;
        #pragma unroll
        for (int t = 0; t < 2; t++) {
            float4 xv = xr[lane * 2 + t];
            float4 cv = cr[lane * 2 + t];
            dot = fmaf(xv.x, cv.x, dot);
            dot = fmaf(xv.y, cv.y, dot);
            dot = fmaf(xv.z, cv.z, dot);
            dot = fmaf(xv.w, cv.w, dot);
        }
        #pragma unroll
        for (int o = 16; o > 0; o >>= 1) dot += __shfl_down_sync(0xFFFFFFFFu, dot, o);
        if (lane == 0) {
            float sc = __fadd_rn(__fadd_rn(g_A[pix], __fmul_rn(-2.0f, dot)), g_cn[k]);
            unsigned long long key =
                ((unsigned long long)float_to_ordered(sc) << 32) | (unsigned long long)k;
            atomicMin(&g_best[pix], key);
        }
    }
}

// ---------------------------------------------------------------------------
// Kernel 6: gather output (NCHW), smem-staged code rows (stride-257,
// conflict-free reads) + per-block loss partial from g_best keys.
// ---------------------------------------------------------------------------
__global__ __launch_bounds__(256)
void gather_kernel(const float* __restrict__ C, float* __restrict__ out) {
    __shared__ float rows[32][257];
    __shared__ int s_k[32];
    const int tid = threadIdx.x, lane = tid & 31, wid = tid >> 5;
    const int b  = blockIdx.x >> 5;
    const int pB = (blockIdx.x & 31) * 32;

    if (tid < 32) {
        unsigned long long key = g_best[b * HW_ + pB + tid];
        s_k[tid] = (int)(unsigned int)(key & 1023u);
        // loss partial: sum of the 32 per-pixel min scores
        float sc = ordered_to_float((unsigned)(key >> 32));
        #pragma unroll
        for (int o = 16; o > 0; o >>= 1) sc += __shfl_down_sync(0xFFFFFFFFu, sc, o);
        if (tid == 0) g_part[blockIdx.x] = sc;
    }
    __syncthreads();

    const float4* C4 = reinterpret_cast<const float4*>(C);
    #pragma unroll
    for (int i = 0; i < 8; i++) {
        int idx = i * 256 + tid;          // 0..2047
        int r = idx >> 6, c = idx & 63;
        float4 v = C4[s_k[r] * 64 + c];
        rows[r][c * 4 + 0] = v.x;
        rows[r][c * 4 + 1] = v.y;
        rows[r][c * 4 + 2] = v.z;
        rows[r][c * 4 + 3] = v.w;
    }
    __syncthreads();

    float* ob = out + (size_t)b * D_ * HW_ + pB;
    #pragma unroll
    for (int it = 0; it < 32; it++) {
        int d = it * 8 + wid;
        ob[(size_t)d * HW_ + lane] = rows[lane][d];
    }
}

// ---------------------------------------------------------------------------
// Kernel 7: loss = 1.25 * sum(g_part) / NELM  (2048 partials, deterministic).
// ---------------------------------------------------------------------------
__global__ __launch_bounds__(1024)
void finalize_kernel(float* __restrict__ out, int loss_idx) {
    __shared__ double red[1024];
    double s = 0.0;
    for (int i = threadIdx.x; i < NPIX / 32; i += 1024)
        s += (double)g_part[i];
    red[threadIdx.x] = s;
    __syncthreads();
    for (int o = 512; o > 0; o >>= 1) {
        if (threadIdx.x < o) red[threadIdx.x] += red[threadIdx.x + o];
        __syncthreads();
    }
    if (threadIdx.x == 0)
        out[loss_idx] = (float)(1.25 * red[0] / (double)NELM);
}

// ---------------------------------------------------------------------------
extern "C" void kernel_launch(void* const* d_in, const int* in_sizes, int n_in,
                              void* d_out, int out_size) {
    const float* X = (const float*)d_in[0];   // [64,256,32,32] f32 NCHW
    const float* C = (const float*)d_in[1];   // [1024,256] f32
    float* out = (float*)d_out;

    static const int SMEM_BYTES = 196608 + 1024;   // A + 2xB (+ align slack)
    cudaFuncSetAttribute(vq_mma_kernel,
                         cudaFuncAttributeMaxDynamicSharedMemorySize, SMEM_BYTES);

    cn_cbf_kernel<<<K_ / 32, 256>>>(C);
    a_kernel<<<NPIX / 256, 256>>>(X);
    transpose_kernel<<<dim3(HW_ / 32, D_ / 32, B_), dim3(32, 8)>>>(X);
    vq_mma_kernel<<<NPIX / 128, 512, SMEM_BYTES>>>();
    rescore_kernel<<<512, 256>>>(C);
    gather_kernel<<<NPIX / 32, 256>>>(C, out);
    if (out_size > NELM) {
        finalize_kernel<<<1, 1024>>>(out, out_size - 1);
    }
}

// round 16
// speedup vs baseline: 1.3498x; 1.0538x over previous
#include <cuda_runtime.h>
#include <cuda_bf16.h>
#include <cstdint>

// Problem constants (fixed for this dataset)
#define B_   64
#define D_   256
#define HW_  1024            // 32*32
#define K_   1024            // num embeddings
#define NPIX (B_ * HW_)      // 65536
#define NELM (B_ * D_ * HW_) // 16777216
#define CAND_CAP 1048576
#define EPS_MARGIN 5e-3f
#define STAGE_CAP 1024

// ---------------------------------------------------------------------------
// Scratch (device globals; no cudaMalloc allowed)
// ---------------------------------------------------------------------------
__device__ unsigned long long g_best[NPIX];   // packed (orderable_score<<32)|k
__device__ float g_cn[K_];                    // |c_k|^2 (exact sequential chain)
__device__ float g_A[NPIX];                   // |x_n|^2 (exact sequential chain)
__device__ float g_Xt[NPIX * D_];             // X transposed: [pix][d] fp32
__device__ __nv_bfloat16 g_Xt_bf[NPIX * D_];  // bf16 copy
__device__ __nv_bfloat16 g_Cbf[K_ * D_];      // codebook bf16
__device__ unsigned long long g_cand[CAND_CAP]; // (score_bits<<32)|(pix<<10)|k
__device__ unsigned int g_ncand;
__device__ float g_part[NPIX / 32];           // per-gather-block loss partials

__device__ __forceinline__ unsigned int float_to_ordered(float f) {
    unsigned int u = __float_as_uint(f);
    return (u & 0x80000000u) ? ~u : (u | 0x80000000u);
}
__device__ __forceinline__ float ordered_to_float(unsigned int o) {
    unsigned int u = (o & 0x80000000u) ? (o & 0x7FFFFFFFu) : ~o;
    return __uint_as_float(u);
}

__device__ __forceinline__ uint32_t smem_u32(const void* p) {
    uint32_t a;
    asm("{ .reg .u64 t; cvta.to.shared.u64 t, %1; cvt.u32.u64 %0, t; }"
        : "=r"(a) : "l"(p));
    return a;
}

// cp.async 16B (sm_80+, legal on plain sm_103 target)
__device__ __forceinline__ void cp16(uint32_t saddr, const void* g) {
    asm volatile("cp.async.cg.shared.global [%0], [%1], 16;"
                 :: "r"(saddr), "l"(g) : "memory");
}

// ldmatrix x4 (non-transposed, b16)
__device__ __forceinline__ void ldm_x4(uint32_t* r, uint32_t addr) {
    asm volatile("ldmatrix.sync.aligned.m8n8.x4.shared.b16 {%0,%1,%2,%3}, [%4];"
                 : "=r"(r[0]), "=r"(r[1]), "=r"(r[2]), "=r"(r[3]) : "r"(addr));
}

// bf16 HMMA m16n8k16, f32 accumulate (sm_80+)
__device__ __forceinline__ void mma_bf16(float* c, const uint32_t* a,
                                         uint32_t b0, uint32_t b1) {
    asm volatile(
        "mma.sync.aligned.m16n8k16.row.col.f32.bf16.bf16.f32 "
        "{%0,%1,%2,%3}, {%4,%5,%6,%7}, {%8,%9}, {%0,%1,%2,%3};"
        : "+f"(c[0]), "+f"(c[1]), "+f"(c[2]), "+f"(c[3])
        : "r"(a[0]), "r"(a[1]), "r"(a[2]), "r"(a[3]), "r"(b0), "r"(b1));
}

// ---------------------------------------------------------------------------
// Kernel 1: |c_k|^2 (exact sequential chain) + bf16 convert, coalesced.
// ---------------------------------------------------------------------------
__global__ __launch_bounds__(256)
void cn_cbf_kernel(const float* __restrict__ C) {
    __shared__ float rows[32][257];
    const int tid = threadIdx.x;
    const int kb = blockIdx.x * 32;
    if (blockIdx.x == 0 && tid == 0) g_ncand = 0;

    const float4* C4 = reinterpret_cast<const float4*>(C + (size_t)kb * D_);
    uint2* B2 = reinterpret_cast<uint2*>(g_Cbf + (size_t)kb * D_);
    #pragma unroll
    for (int i = 0; i < 8; i++) {
        int idx = i * 256 + tid;          // float4 index: 0..2047
        int r = idx >> 6, c = idx & 63;   // 64 float4 per row
        float4 v = C4[idx];
        rows[r][c * 4 + 0] = v.x;
        rows[r][c * 4 + 1] = v.y;
        rows[r][c * 4 + 2] = v.z;
        rows[r][c * 4 + 3] = v.w;
        __nv_bfloat162 h01 = __floats2bfloat162_rn(v.x, v.y);
        __nv_bfloat162 h23 = __floats2bfloat162_rn(v.z, v.w);
        uint2 pk;
        pk.x = *reinterpret_cast<unsigned int*>(&h01);
        pk.y = *reinterpret_cast<unsigned int*>(&h23);
        B2[idx] = pk;
    }
    __syncthreads();
    if (tid < 32) {
        float s = 0.f;
        #pragma unroll 8
        for (int d = 0; d < D_; d++) {
            float v = rows[tid][d];
            s = __fadd_rn(s, __fmul_rn(v, v));
        }
        g_cn[kb + tid] = s;
    }
}

// ---------------------------------------------------------------------------
// Kernel 2: |x_p|^2 (exact sequential chain). 256x256, coalesced.
// ---------------------------------------------------------------------------
__global__ __launch_bounds__(256)
void a_kernel(const float* __restrict__ X) {
    const int pix = blockIdx.x * 256 + threadIdx.x;
    const int b = pix >> 10, p = pix & 1023;
    const float* Xb = X + (size_t)b * D_ * HW_ + p;
    float s = 0.f;
    #pragma unroll 8
    for (int d = 0; d < D_; d++) {
        float v = Xb[(size_t)d * HW_];
        s = __fadd_rn(s, __fmul_rn(v, v));
    }
    g_A[pix] = s;
}

// ---------------------------------------------------------------------------
// Kernel 3: transpose X NCHW [b][d][p] -> pixel-major [pix][d], f32+bf16
// ---------------------------------------------------------------------------
__global__ __launch_bounds__(256)
void transpose_kernel(const float* __restrict__ X) {
    __shared__ float t[32][33];
    const int b  = blockIdx.z;
    const int dB = blockIdx.y * 32;
    const int pB = blockIdx.x * 32;
    const int tx = threadIdx.x;       // 0..31
    const int ty = threadIdx.y;       // 0..7

    const float* src = X + ((size_t)b * D_ + dB) * HW_ + pB;
    #pragma unroll
    for (int i = 0; i < 32; i += 8)
        t[ty + i][tx] = src[(size_t)(ty + i) * HW_ + tx];
    __syncthreads();

    const size_t obase = ((size_t)(b * HW_ + pB)) * D_ + dB;
    #pragma unroll
    for (int i = 0; i < 32; i += 8) {
        int row = ty + i;
        float v = t[tx][row];
        g_Xt[obase + (size_t)row * D_ + tx] = v;
        g_Xt_bf[obase + (size_t)row * D_ + tx] = __float2bfloat16(v);
    }
}

// ---------------------------------------------------------------------------
// Kernel 4: persistent-A bf16 HMMA GEMM, 128 pixels x ALL 1024 codes per CTA.
// OCCUPANCY RETEST vs R13: 256 threads / 8 warps, SAME 32x32 warp tile
// (4m x 2n), k-tiles of 64 codes (16 iters), single-buffered 32KB B tile.
// Smem ~112KB/CTA -> 2 CTAs/SM: two independent barrier domains overlap each
// other's kt-barrier/epilogue/B-load stalls. All numerics identical to R13.
// ---------------------------------------------------------------------------
__global__ __launch_bounds__(256, 2)
void vq_mma_kernel() {
    extern __shared__ char dsm_raw[];
    __shared__ float s_cn[K_];
    __shared__ float s_A[128];
    __shared__ unsigned int s_min[128];
    __shared__ unsigned int s_pcount[128];
    __shared__ unsigned long long stage[STAGE_CAP];
    __shared__ unsigned int s_cnt;

    const int tid = threadIdx.x, lane = tid & 31, wid = tid >> 5;
    const int pt = blockIdx.x;   // 0..511 pixel tiles (128 pixels each)

    const uint32_t s0 = smem_u32(dsm_raw);
    const uint32_t base = (s0 + 127) & ~127u;   // 128B align (bank-pattern safe)
    const uint32_t sA = base;                   // 64KB: 128 px rows
    const uint32_t sB = base + 65536;           // 32KB: 64 code rows

    #pragma unroll
    for (int i = 0; i < 4; i++) s_cn[tid + i * 256] = g_cn[tid + i * 256];
    if (tid < 128) {
        s_min[tid] = 0xFFFFFFFFu;
        s_pcount[tid] = 0u;
        s_A[tid] = g_A[pt * 128 + tid];
        g_best[pt * 128 + tid] = 0xFFFFFFFFFFFFFFFFull;
    }
    if (tid == 0) s_cnt = 0;

    // Stage A (once, 4096 chunks) + B tile 0 (2048 chunks)
    const __nv_bfloat16* gA = g_Xt_bf + (size_t)pt * 128 * D_;
    #pragma unroll
    for (int i = 0; i < 16; i++) {
        int v = i * 256 + tid;             // 0..4095 16B chunks
        int r = v >> 5, c = v & 31;
        uint32_t off = (uint32_t)(r * 512) + (((uint32_t)c * 16) ^ ((uint32_t)(r & 7) << 4));
        cp16(sA + off, gA + (size_t)v * 8);
    }
    #pragma unroll
    for (int i = 0; i < 8; i++) {
        int v = i * 256 + tid;             // 0..2047 16B chunks
        int r = v >> 5, c = v & 31;
        uint32_t off = (uint32_t)(r * 512) + (((uint32_t)c * 16) ^ ((uint32_t)(r & 7) << 4));
        cp16(sB + off, g_Cbf + (size_t)v * 8);
    }
    asm volatile("cp.async.commit_group;");

    // Warp tiling: 4 (m) x 2 (n), 32x32 per warp — the R13-validated shape
    const int wm = (wid & 3) * 32;
    const int wn = (wid >> 2) * 32;
    const int a_row = wm + (lane & 15);
    const uint32_t a_swz = (uint32_t)((a_row & 7) << 4);
    const int a_kb = (lane >> 4) * 16;
    const int b_row = wn + ((lane & 7) | ((lane & 16) >> 1));
    const uint32_t b_swz = (uint32_t)((b_row & 7) << 4);
    const int b_kb = ((lane >> 3) & 1) * 16;

    const int r0b = wm + (lane >> 2);          // score row base (mi adds 16)
    const int c0b = wn + (lane & 3) * 2;       // score col base (nt adds 8)

    const uint32_t aAddr0 = sA + (uint32_t)a_row * 512;
    const uint32_t aAddr1 = sA + (uint32_t)(a_row + 16) * 512;
    const uint32_t bAddr0 = sB + (uint32_t)b_row * 512;
    const uint32_t bAddr1 = sB + (uint32_t)(b_row + 16) * 512;

    for (int kt = 0; kt < 16; kt++) {
        asm volatile("cp.async.wait_group 0;" ::: "memory");
        __syncthreads();   // B_kt visible to all warps

        float acc[2][4][4];
        #pragma unroll
        for (int mi = 0; mi < 2; mi++)
            #pragma unroll
            for (int nt = 0; nt < 4; nt++)
                #pragma unroll
                for (int e = 0; e < 4; e++) acc[mi][nt][e] = 0.f;

        // 2-stage register fragment pipeline over ks
        uint32_t afb[2][2][4], bfb[2][2][4];
        {
            uint32_t ka = (uint32_t)a_kb ^ a_swz;
            uint32_t kb = (uint32_t)b_kb ^ b_swz;
            ldm_x4(afb[0][0], aAddr0 + ka);
            ldm_x4(afb[0][1], aAddr1 + ka);
            ldm_x4(bfb[0][0], bAddr0 + kb);
            ldm_x4(bfb[0][1], bAddr1 + kb);
        }
        #pragma unroll
        for (int ks = 0; ks < 16; ks++) {
            const int cur = ks & 1, nxt = cur ^ 1;
            if (ks < 15) {
                uint32_t ka = ((uint32_t)((ks + 1) * 32 + a_kb)) ^ a_swz;
                uint32_t kb = ((uint32_t)((ks + 1) * 32 + b_kb)) ^ b_swz;
                ldm_x4(afb[nxt][0], aAddr0 + ka);
                ldm_x4(afb[nxt][1], aAddr1 + ka);
                ldm_x4(bfb[nxt][0], bAddr0 + kb);
                ldm_x4(bfb[nxt][1], bAddr1 + kb);
            }
            #pragma unroll
            for (int mi = 0; mi < 2; mi++)
                #pragma unroll
                for (int nt = 0; nt < 4; nt++)
                    mma_bf16(acc[mi][nt], afb[cur][mi],
                             bfb[cur][nt >> 1][(nt & 1) * 2],
                             bfb[cur][nt >> 1][(nt & 1) * 2 + 1]);
        }

        // Scores IN PLACE: acc <- cn[k] - 2*acc. Update per-pixel running min.
        #pragma unroll
        for (int mi = 0; mi < 2; mi++) {
            float m0 = 3.4e38f, m1 = 3.4e38f;
            #pragma unroll
            for (int nt = 0; nt < 4; nt++) {
                int c0 = c0b + nt * 8;
                float cn0 = s_cn[kt * 64 + c0], cn1 = s_cn[kt * 64 + c0 + 1];
                acc[mi][nt][0] = fmaf(-2.f, acc[mi][nt][0], cn0);
                acc[mi][nt][1] = fmaf(-2.f, acc[mi][nt][1], cn1);
                acc[mi][nt][2] = fmaf(-2.f, acc[mi][nt][2], cn0);
                acc[mi][nt][3] = fmaf(-2.f, acc[mi][nt][3], cn1);
                m0 = fminf(m0, fminf(acc[mi][nt][0], acc[mi][nt][1]));
                m1 = fminf(m1, fminf(acc[mi][nt][2], acc[mi][nt][3]));
            }
            m0 = fminf(m0, __shfl_xor_sync(0xFFFFFFFFu, m0, 1));
            m0 = fminf(m0, __shfl_xor_sync(0xFFFFFFFFu, m0, 2));
            m1 = fminf(m1, __shfl_xor_sync(0xFFFFFFFFu, m1, 1));
            m1 = fminf(m1, __shfl_xor_sync(0xFFFFFFFFu, m1, 2));
            if ((lane & 3) == 0) {
                atomicMin(&s_min[r0b + mi * 16],     float_to_ordered(m0));
                atomicMin(&s_min[r0b + mi * 16 + 8], float_to_ordered(m1));
            }
        }
        // NO extra sync: stale (larger) min still yields a candidate superset.

        // Emit candidates vs running min (per-thread, rare-divergent)
        const unsigned pixb = (unsigned)(pt * 128);
        #pragma unroll
        for (int mi = 0; mi < 2; mi++) {
            int r0 = r0b + mi * 16;
            float thr0 = ordered_to_float(s_min[r0]) + EPS_MARGIN;
            float thr1 = ordered_to_float(s_min[r0 + 8]) + EPS_MARGIN;
            #pragma unroll
            for (int nt = 0; nt < 4; nt++) {
                int c0 = c0b + nt * 8;
                #pragma unroll
                for (int e = 0; e < 4; e++) {
                    float v = acc[mi][nt][e];
                    float thr = (e < 2) ? thr0 : thr1;
                    if (v <= thr) {
                        unsigned row = (unsigned)(r0 + ((e < 2) ? 0 : 8));
                        unsigned k = (unsigned)(kt * 64 + c0 + (e & 1));
                        unsigned long long entry =
                            ((unsigned long long)__float_as_uint(v) << 32) |
                            ((unsigned long long)(pixb + row) << 10) | k;
                        unsigned slot = atomicAdd(&s_cnt, 1u);
                        if (slot < STAGE_CAP) stage[slot] = entry;
                        else {
                            unsigned gs = atomicAdd(&g_ncand, 1u);
                            if (gs < CAND_CAP) g_cand[gs] = entry;
                        }
                    }
                }
            }
        }
        __syncthreads();   // all warps done reading sB before overwrite

        // Issue next B tile (single buffer; sibling CTA hides the latency)
        if (kt + 1 < 16) {
            const __nv_bfloat16* gBn = g_Cbf + (size_t)(kt + 1) * 64 * D_;
            #pragma unroll
            for (int i = 0; i < 8; i++) {
                int v = i * 256 + tid;
                int r = v >> 5, c = v & 31;
                uint32_t off = (uint32_t)(r * 512) +
                               (((uint32_t)c * 16) ^ ((uint32_t)(r & 7) << 4));
                cp16(sB + off, gBn + (size_t)v * 8);
            }
            asm volatile("cp.async.commit_group;");
        }
    }
    __syncthreads();

    // Final flush, pass 1: count final-filtered candidates per pixel
    const unsigned total = min(s_cnt, (unsigned)STAGE_CAP);
    const bool oflow = (s_cnt > (unsigned)STAGE_CAP);
    for (unsigned i = tid; i < total; i += 256) {
        unsigned long long e = stage[i];
        float v = __uint_as_float((unsigned)(e >> 32));
        unsigned row = ((unsigned)e >> 10) & 127u;
        if (v <= ordered_to_float(s_min[row]) + EPS_MARGIN)
            atomicAdd(&s_pcount[row], 1u);
    }
    __syncthreads();

    // Pass 2: singles -> direct g_best write (full score A + filter score);
    //         multis -> g_cand for exact rescoring.
    const unsigned rounded = (total + 255u) & ~255u;
    for (unsigned i = tid; i < rounded; i += 256) {
        bool pred = false;
        unsigned long long e = 0;
        if (i < total) {
            e = stage[i];
            float v = __uint_as_float((unsigned)(e >> 32));
            unsigned low = (unsigned)e;
            unsigned row = (low >> 10) & 127u;
            if (v <= ordered_to_float(s_min[row]) + EPS_MARGIN) {
                if (s_pcount[row] == 1u && !oflow) {
                    unsigned pix = low >> 10, k = low & 1023u;
                    float full = __fadd_rn(s_A[row], v);   // A + (cn - 2dot)
                    unsigned long long key =
                        ((unsigned long long)float_to_ordered(full) << 32) |
                        (unsigned long long)k;
                    atomicMin(&g_best[pix], key);
                } else {
                    pred = true;
                }
            }
        }
        unsigned mask = __ballot_sync(0xFFFFFFFFu, pred);
        if (mask) {
            int leader = __ffs(mask) - 1;
            unsigned bidx = 0;
            if (lane == leader) bidx = atomicAdd(&g_ncand, (unsigned)__popc(mask));
            bidx = __shfl_sync(0xFFFFFFFFu, bidx, leader);
            if (pred) {
                unsigned dst = bidx + __popc(mask & ((1u << lane) - 1u));
                if (dst < CAND_CAP) g_cand[dst] = e;
            }
        }
    }
}

// ---------------------------------------------------------------------------
// Kernel 5: exact fp32 rescore of multi-candidate entries (one warp each).
// score = fl(fl(A - 2*dot) + cn)  — the Round-2-validated rounding chain.
// ---------------------------------------------------------------------------
__global__ __launch_bounds__(256)
void rescore_kernel(const float* __restrict__ C) {
    const unsigned int count = min(g_ncand, (unsigned)CAND_CAP);
    const int lane = threadIdx.x & 31;
    const unsigned gw = (blockIdx.x * blockDim.x + threadIdx.x) >> 5;
    const unsigned nw = (gridDim.x * blockDim.x) >> 5;

    for (unsigned i = gw; i < count; i += nw) {
        unsigned long long e = g_cand[i];
        unsigned low = (unsigned)e;
        unsigned pix = low >> 10, k = low & 1023u;

        const float4* xr = reinterpret_cast<const float4*>(g_Xt + (size_t)pix * D_);
        const float4* cr = reinterpret_cast<const float4*>(C + (size_t)k * D_);
        float dot = 0.f;
        #pragma unroll
        for (int t = 0; t < 2; t++) {
            float4 xv = xr[lane * 2 + t];
            float4 cv = cr[lane * 2 + t];
            dot = fmaf(xv.x, cv.x, dot);
            dot = fmaf(xv.y, cv.y, dot);
            dot = fmaf(xv.z, cv.z, dot);
            dot = fmaf(xv.w, cv.w, dot);
        }
        #pragma unroll
        for (int o = 16; o > 0; o >>= 1) dot += __shfl_down_sync(0xFFFFFFFFu, dot, o);
        if (lane == 0) {
            float sc = __fadd_rn(__fadd_rn(g_A[pix], __fmul_rn(-2.0f, dot)), g_cn[k]);
            unsigned long long key =
                ((unsigned long long)float_to_ordered(sc) << 32) | (unsigned long long)k;
            atomicMin(&g_best[pix], key);
        }
    }
}

// ---------------------------------------------------------------------------
// Kernel 6: gather output (NCHW), smem-staged code rows (stride-257,
// conflict-free reads) + per-block loss partial from g_best keys.
// ---------------------------------------------------------------------------
__global__ __launch_bounds__(256)
void gather_kernel(const float* __restrict__ C, float* __restrict__ out) {
    __shared__ float rows[32][257];
    __shared__ int s_k[32];
    const int tid = threadIdx.x, lane = tid & 31, wid = tid >> 5;
    const int b  = blockIdx.x >> 5;
    const int pB = (blockIdx.x & 31) * 32;

    if (tid < 32) {
        unsigned long long key = g_best[b * HW_ + pB + tid];
        s_k[tid] = (int)(unsigned int)(key & 1023u);
        float sc = ordered_to_float((unsigned)(key >> 32));
        #pragma unroll
        for (int o = 16; o > 0; o >>= 1) sc += __shfl_down_sync(0xFFFFFFFFu, sc, o);
        if (tid == 0) g_part[blockIdx.x] = sc;
    }
    __syncthreads();

    const float4* C4 = reinterpret_cast<const float4*>(C);
    #pragma unroll
    for (int i = 0; i < 8; i++) {
        int idx = i * 256 + tid;          // 0..2047
        int r = idx >> 6, c = idx & 63;
        float4 v = C4[s_k[r] * 64 + c];
        rows[r][c * 4 + 0] = v.x;
        rows[r][c * 4 + 1] = v.y;
        rows[r][c * 4 + 2] = v.z;
        rows[r][c * 4 + 3] = v.w;
    }
    __syncthreads();

    float* ob = out + (size_t)b * D_ * HW_ + pB;
    #pragma unroll
    for (int it = 0; it < 32; it++) {
        int d = it * 8 + wid;
        ob[(size_t)d * HW_ + lane] = rows[lane][d];
    }
}

// ---------------------------------------------------------------------------
// Kernel 7: loss = 1.25 * sum(g_part) / NELM  (2048 partials, deterministic).
// ---------------------------------------------------------------------------
__global__ __launch_bounds__(1024)
void finalize_kernel(float* __restrict__ out, int loss_idx) {
    __shared__ double red[1024];
    double s = 0.0;
    for (int i = threadIdx.x; i < NPIX / 32; i += 1024)
        s += (double)g_part[i];
    red[threadIdx.x] = s;
    __syncthreads();
    for (int o = 512; o > 0; o >>= 1) {
        if (threadIdx.x < o) red[threadIdx.x] += red[threadIdx.x + o];
        __syncthreads();
    }
    if (threadIdx.x == 0)
        out[loss_idx] = (float)(1.25 * red[0] / (double)NELM);
}

// ---------------------------------------------------------------------------
extern "C" void kernel_launch(void* const* d_in, const int* in_sizes, int n_in,
                              void* d_out, int out_size) {
    const float* X = (const float*)d_in[0];   // [64,256,32,32] f32 NCHW
    const float* C = (const float*)d_in[1];   // [1024,256] f32
    float* out = (float*)d_out;

    static const int SMEM_BYTES = 98304 + 128;   // A(64K) + B(32K) + align slack
    cudaFuncSetAttribute(vq_mma_kernel,
                         cudaFuncAttributeMaxDynamicSharedMemorySize, SMEM_BYTES);

    cn_cbf_kernel<<<K_ / 32, 256>>>(C);
    a_kernel<<<NPIX / 256, 256>>>(X);
    transpose_kernel<<<dim3(HW_ / 32, D_ / 32, B_), dim3(32, 8)>>>(X);
    vq_mma_kernel<<<NPIX / 128, 256, SMEM_BYTES>>>();
    rescore_kernel<<<512, 256>>>(C);
    gather_kernel<<<NPIX / 32, 256>>>(C, out);
    if (out_size > NELM) {
        finalize_kernel<<<1, 1024>>>(out, out_size - 1);
    }
}

// round 17
// speedup vs baseline: 1.3887x; 1.0288x over previous
#include <cuda_runtime.h>
#include <cuda_bf16.h>
#include <cstdint>

// Problem constants (fixed for this dataset)
#define B_   64
#define D_   256
#define HW_  1024            // 32*32
#define K_   1024            // num embeddings
#define NPIX (B_ * HW_)      // 65536
#define NELM (B_ * D_ * HW_) // 16777216
#define CAND_CAP 1048576
#define EPS_MARGIN 5e-3f
#define STAGE_CAP 1024

// ---------------------------------------------------------------------------
// Scratch (device globals; no cudaMalloc allowed)
// ---------------------------------------------------------------------------
__device__ unsigned long long g_best[NPIX];   // packed (orderable_score<<32)|k
__device__ float g_cn[K_];                    // |c_k|^2 (exact sequential chain)
__device__ float g_A[NPIX];                   // |x_n|^2 (exact sequential chain)
__device__ float g_Xt[NPIX * D_];             // X transposed: [pix][d] fp32
__device__ __nv_bfloat16 g_Xt_bf[NPIX * D_];  // bf16 copy
__device__ __nv_bfloat16 g_Cbf[K_ * D_];      // codebook bf16
__device__ unsigned long long g_cand[CAND_CAP]; // (score_bits<<32)|(pix<<10)|k
__device__ unsigned int g_ncand;
__device__ float g_part[NPIX / 32];           // per-gather-block loss partials

__device__ __forceinline__ unsigned int float_to_ordered(float f) {
    unsigned int u = __float_as_uint(f);
    return (u & 0x80000000u) ? ~u : (u | 0x80000000u);
}
__device__ __forceinline__ float ordered_to_float(unsigned int o) {
    unsigned int u = (o & 0x80000000u) ? (o & 0x7FFFFFFFu) : ~o;
    return __uint_as_float(u);
}

__device__ __forceinline__ uint32_t smem_u32(const void* p) {
    uint32_t a;
    asm("{ .reg .u64 t; cvta.to.shared.u64 t, %1; cvt.u32.u64 %0, t; }"
        : "=r"(a) : "l"(p));
    return a;
}

// cp.async 16B (sm_80+, legal on plain sm_103 target)
__device__ __forceinline__ void cp16(uint32_t saddr, const void* g) {
    asm volatile("cp.async.cg.shared.global [%0], [%1], 16;"
                 :: "r"(saddr), "l"(g) : "memory");
}

// ldmatrix x4 (non-transposed, b16)
__device__ __forceinline__ void ldm_x4(uint32_t* r, uint32_t addr) {
    asm volatile("ldmatrix.sync.aligned.m8n8.x4.shared.b16 {%0,%1,%2,%3}, [%4];"
                 : "=r"(r[0]), "=r"(r[1]), "=r"(r[2]), "=r"(r[3]) : "r"(addr));
}

// bf16 HMMA m16n8k16, f32 accumulate (sm_80+)
__device__ __forceinline__ void mma_bf16(float* c, const uint32_t* a,
                                         uint32_t b0, uint32_t b1) {
    asm volatile(
        "mma.sync.aligned.m16n8k16.row.col.f32.bf16.bf16.f32 "
        "{%0,%1,%2,%3}, {%4,%5,%6,%7}, {%8,%9}, {%0,%1,%2,%3};"
        : "+f"(c[0]), "+f"(c[1]), "+f"(c[2]), "+f"(c[3])
        : "r"(a[0]), "r"(a[1]), "r"(a[2]), "r"(a[3]), "r"(b0), "r"(b1));
}

// ---------------------------------------------------------------------------
// Kernel 1: |c_k|^2 (exact sequential chain) + bf16 convert, coalesced.
// ---------------------------------------------------------------------------
__global__ __launch_bounds__(256)
void cn_cbf_kernel(const float* __restrict__ C) {
    __shared__ float rows[32][257];
    const int tid = threadIdx.x;
    const int kb = blockIdx.x * 32;
    if (blockIdx.x == 0 && tid == 0) g_ncand = 0;

    const float4* C4 = reinterpret_cast<const float4*>(C + (size_t)kb * D_);
    uint2* B2 = reinterpret_cast<uint2*>(g_Cbf + (size_t)kb * D_);
    #pragma unroll
    for (int i = 0; i < 8; i++) {
        int idx = i * 256 + tid;          // float4 index: 0..2047
        int r = idx >> 6, c = idx & 63;   // 64 float4 per row
        float4 v = C4[idx];
        rows[r][c * 4 + 0] = v.x;
        rows[r][c * 4 + 1] = v.y;
        rows[r][c * 4 + 2] = v.z;
        rows[r][c * 4 + 3] = v.w;
        __nv_bfloat162 h01 = __floats2bfloat162_rn(v.x, v.y);
        __nv_bfloat162 h23 = __floats2bfloat162_rn(v.z, v.w);
        uint2 pk;
        pk.x = *reinterpret_cast<unsigned int*>(&h01);
        pk.y = *reinterpret_cast<unsigned int*>(&h23);
        B2[idx] = pk;
    }
    __syncthreads();
    if (tid < 32) {
        float s = 0.f;
        #pragma unroll 8
        for (int d = 0; d < D_; d++) {
            float v = rows[tid][d];
            s = __fadd_rn(s, __fmul_rn(v, v));
        }
        g_cn[kb + tid] = s;
    }
}

// ---------------------------------------------------------------------------
// Kernel 2 (FUSED prep): reads X once; produces g_Xt (f32 pixel-major),
// g_Xt_bf (bf16), and g_A (|x|^2, exact ascending-d sequential chain).
// Block = 256 pixels of one batch; 8 chunks of 32 d staged in smem.
// ---------------------------------------------------------------------------
__global__ __launch_bounds__(256)
void prep_kernel(const float* __restrict__ X) {
    __shared__ float t[32][257];
    const int tid = threadIdx.x, lane = tid & 31, wid = tid >> 5;
    const int b  = blockIdx.x >> 2;
    const int pB = (blockIdx.x & 3) * 256;

    const float* Xb = X + (size_t)b * D_ * HW_ + pB;
    const size_t obase = ((size_t)(b * HW_ + pB)) * D_;

    float a = 0.f;
    for (int chunk = 0; chunk < 8; chunk++) {
        const int dBase = chunk * 32;
        // Load 32 d-rows x 256 px, coalesced
        #pragma unroll
        for (int dd = 0; dd < 32; dd++)
            t[dd][tid] = Xb[(size_t)(dBase + dd) * HW_ + tid];
        __syncthreads();

        // A chain: ascending d within chunk, chunks ascending -> exact order
        #pragma unroll 8
        for (int dd = 0; dd < 32; dd++) {
            float v = t[dd][tid];
            a = __fadd_rn(a, __fmul_rn(v, v));
        }

        // Write pixel-major rows: warp w covers pixel row (it*8+w), lanes = d
        #pragma unroll
        for (int it = 0; it < 32; it++) {
            int row = it * 8 + wid;                 // pixel 0..255
            float v = t[lane][row];                 // bank (lane+row)%32: free
            g_Xt[obase + (size_t)row * D_ + dBase + lane] = v;
            g_Xt_bf[obase + (size_t)row * D_ + dBase + lane] = __float2bfloat16(v);
        }
        __syncthreads();
    }
    g_A[b * HW_ + pB + tid] = a;
}

// ---------------------------------------------------------------------------
// Kernel 3: persistent-A bf16 HMMA GEMM, 128 pixels x ALL 1024 codes per CTA.
// 256 threads / 8 warps, 32x32 warp tile (4m x 2n), 64-code k-tiles (16 it),
// single-buffered 32KB B tile, 2 CTAs/SM. (R16-validated 144.6us config.)
// ---------------------------------------------------------------------------
__global__ __launch_bounds__(256, 2)
void vq_mma_kernel() {
    extern __shared__ char dsm_raw[];
    __shared__ float s_cn[K_];
    __shared__ float s_A[128];
    __shared__ unsigned int s_min[128];
    __shared__ unsigned int s_pcount[128];
    __shared__ unsigned long long stage[STAGE_CAP];
    __shared__ unsigned int s_cnt;

    const int tid = threadIdx.x, lane = tid & 31, wid = tid >> 5;
    const int pt = blockIdx.x;   // 0..511 pixel tiles (128 pixels each)

    const uint32_t s0 = smem_u32(dsm_raw);
    const uint32_t base = (s0 + 127) & ~127u;
    const uint32_t sA = base;                   // 64KB: 128 px rows
    const uint32_t sB = base + 65536;           // 32KB: 64 code rows

    #pragma unroll
    for (int i = 0; i < 4; i++) s_cn[tid + i * 256] = g_cn[tid + i * 256];
    if (tid < 128) {
        s_min[tid] = 0xFFFFFFFFu;
        s_pcount[tid] = 0u;
        s_A[tid] = g_A[pt * 128 + tid];
        g_best[pt * 128 + tid] = 0xFFFFFFFFFFFFFFFFull;
    }
    if (tid == 0) s_cnt = 0;

    // Stage A (once, 4096 chunks) + B tile 0 (2048 chunks)
    const __nv_bfloat16* gA = g_Xt_bf + (size_t)pt * 128 * D_;
    #pragma unroll
    for (int i = 0; i < 16; i++) {
        int v = i * 256 + tid;             // 0..4095 16B chunks
        int r = v >> 5, c = v & 31;
        uint32_t off = (uint32_t)(r * 512) + (((uint32_t)c * 16) ^ ((uint32_t)(r & 7) << 4));
        cp16(sA + off, gA + (size_t)v * 8);
    }
    #pragma unroll
    for (int i = 0; i < 8; i++) {
        int v = i * 256 + tid;             // 0..2047 16B chunks
        int r = v >> 5, c = v & 31;
        uint32_t off = (uint32_t)(r * 512) + (((uint32_t)c * 16) ^ ((uint32_t)(r & 7) << 4));
        cp16(sB + off, g_Cbf + (size_t)v * 8);
    }
    asm volatile("cp.async.commit_group;");

    // Warp tiling: 4 (m) x 2 (n), 32x32 per warp
    const int wm = (wid & 3) * 32;
    const int wn = (wid >> 2) * 32;
    const int a_row = wm + (lane & 15);
    const uint32_t a_swz = (uint32_t)((a_row & 7) << 4);
    const int a_kb = (lane >> 4) * 16;
    const int b_row = wn + ((lane & 7) | ((lane & 16) >> 1));
    const uint32_t b_swz = (uint32_t)((b_row & 7) << 4);
    const int b_kb = ((lane >> 3) & 1) * 16;

    const int r0b = wm + (lane >> 2);          // score row base (mi adds 16)
    const int c0b = wn + (lane & 3) * 2;       // score col base (nt adds 8)

    const uint32_t aAddr0 = sA + (uint32_t)a_row * 512;
    const uint32_t aAddr1 = sA + (uint32_t)(a_row + 16) * 512;
    const uint32_t bAddr0 = sB + (uint32_t)b_row * 512;
    const uint32_t bAddr1 = sB + (uint32_t)(b_row + 16) * 512;

    for (int kt = 0; kt < 16; kt++) {
        asm volatile("cp.async.wait_group 0;" ::: "memory");
        __syncthreads();   // B_kt visible to all warps

        float acc[2][4][4];
        #pragma unroll
        for (int mi = 0; mi < 2; mi++)
            #pragma unroll
            for (int nt = 0; nt < 4; nt++)
                #pragma unroll
                for (int e = 0; e < 4; e++) acc[mi][nt][e] = 0.f;

        // 2-stage register fragment pipeline over ks
        uint32_t afb[2][2][4], bfb[2][2][4];
        {
            uint32_t ka = (uint32_t)a_kb ^ a_swz;
            uint32_t kb = (uint32_t)b_kb ^ b_swz;
            ldm_x4(afb[0][0], aAddr0 + ka);
            ldm_x4(afb[0][1], aAddr1 + ka);
            ldm_x4(bfb[0][0], bAddr0 + kb);
            ldm_x4(bfb[0][1], bAddr1 + kb);
        }
        #pragma unroll
        for (int ks = 0; ks < 16; ks++) {
            const int cur = ks & 1, nxt = cur ^ 1;
            if (ks < 15) {
                uint32_t ka = ((uint32_t)((ks + 1) * 32 + a_kb)) ^ a_swz;
                uint32_t kb = ((uint32_t)((ks + 1) * 32 + b_kb)) ^ b_swz;
                ldm_x4(afb[nxt][0], aAddr0 + ka);
                ldm_x4(afb[nxt][1], aAddr1 + ka);
                ldm_x4(bfb[nxt][0], bAddr0 + kb);
                ldm_x4(bfb[nxt][1], bAddr1 + kb);
            }
            #pragma unroll
            for (int mi = 0; mi < 2; mi++)
                #pragma unroll
                for (int nt = 0; nt < 4; nt++)
                    mma_bf16(acc[mi][nt], afb[cur][mi],
                             bfb[cur][nt >> 1][(nt & 1) * 2],
                             bfb[cur][nt >> 1][(nt & 1) * 2 + 1]);
        }

        // Scores IN PLACE: acc <- cn[k] - 2*acc. Update per-pixel running min.
        #pragma unroll
        for (int mi = 0; mi < 2; mi++) {
            float m0 = 3.4e38f, m1 = 3.4e38f;
            #pragma unroll
            for (int nt = 0; nt < 4; nt++) {
                int c0 = c0b + nt * 8;
                float cn0 = s_cn[kt * 64 + c0], cn1 = s_cn[kt * 64 + c0 + 1];
                acc[mi][nt][0] = fmaf(-2.f, acc[mi][nt][0], cn0);
                acc[mi][nt][1] = fmaf(-2.f, acc[mi][nt][1], cn1);
                acc[mi][nt][2] = fmaf(-2.f, acc[mi][nt][2], cn0);
                acc[mi][nt][3] = fmaf(-2.f, acc[mi][nt][3], cn1);
                m0 = fminf(m0, fminf(acc[mi][nt][0], acc[mi][nt][1]));
                m1 = fminf(m1, fminf(acc[mi][nt][2], acc[mi][nt][3]));
            }
            m0 = fminf(m0, __shfl_xor_sync(0xFFFFFFFFu, m0, 1));
            m0 = fminf(m0, __shfl_xor_sync(0xFFFFFFFFu, m0, 2));
            m1 = fminf(m1, __shfl_xor_sync(0xFFFFFFFFu, m1, 1));
            m1 = fminf(m1, __shfl_xor_sync(0xFFFFFFFFu, m1, 2));
            if ((lane & 3) == 0) {
                atomicMin(&s_min[r0b + mi * 16],     float_to_ordered(m0));
                atomicMin(&s_min[r0b + mi * 16 + 8], float_to_ordered(m1));
            }
        }
        // NO extra sync: stale (larger) min still yields a candidate superset.

        // Emit candidates vs running min (per-thread, rare-divergent)
        const unsigned pixb = (unsigned)(pt * 128);
        #pragma unroll
        for (int mi = 0; mi < 2; mi++) {
            int r0 = r0b + mi * 16;
            float thr0 = ordered_to_float(s_min[r0]) + EPS_MARGIN;
            float thr1 = ordered_to_float(s_min[r0 + 8]) + EPS_MARGIN;
            #pragma unroll
            for (int nt = 0; nt < 4; nt++) {
                int c0 = c0b + nt * 8;
                #pragma unroll
                for (int e = 0; e < 4; e++) {
                    float v = acc[mi][nt][e];
                    float thr = (e < 2) ? thr0 : thr1;
                    if (v <= thr) {
                        unsigned row = (unsigned)(r0 + ((e < 2) ? 0 : 8));
                        unsigned k = (unsigned)(kt * 64 + c0 + (e & 1));
                        unsigned long long entry =
                            ((unsigned long long)__float_as_uint(v) << 32) |
                            ((unsigned long long)(pixb + row) << 10) | k;
                        unsigned slot = atomicAdd(&s_cnt, 1u);
                        if (slot < STAGE_CAP) stage[slot] = entry;
                        else {
                            unsigned gs = atomicAdd(&g_ncand, 1u);
                            if (gs < CAND_CAP) g_cand[gs] = entry;
                        }
                    }
                }
            }
        }
        __syncthreads();   // all warps done reading sB before overwrite

        // Issue next B tile (single buffer; sibling CTA hides the latency)
        if (kt + 1 < 16) {
            const __nv_bfloat16* gBn = g_Cbf + (size_t)(kt + 1) * 64 * D_;
            #pragma unroll
            for (int i = 0; i < 8; i++) {
                int v = i * 256 + tid;
                int r = v >> 5, c = v & 31;
                uint32_t off = (uint32_t)(r * 512) +
                               (((uint32_t)c * 16) ^ ((uint32_t)(r & 7) << 4));
                cp16(sB + off, gBn + (size_t)v * 8);
            }
            asm volatile("cp.async.commit_group;");
        }
    }
    __syncthreads();

    // Final flush, pass 1: count final-filtered candidates per pixel
    const unsigned total = min(s_cnt, (unsigned)STAGE_CAP);
    const bool oflow = (s_cnt > (unsigned)STAGE_CAP);
    for (unsigned i = tid; i < total; i += 256) {
        unsigned long long e = stage[i];
        float v = __uint_as_float((unsigned)(e >> 32));
        unsigned row = ((unsigned)e >> 10) & 127u;
        if (v <= ordered_to_float(s_min[row]) + EPS_MARGIN)
            atomicAdd(&s_pcount[row], 1u);
    }
    __syncthreads();

    // Pass 2: singles -> direct g_best write (full score A + filter score);
    //         multis -> g_cand for exact rescoring.
    const unsigned rounded = (total + 255u) & ~255u;
    for (unsigned i = tid; i < rounded; i += 256) {
        bool pred = false;
        unsigned long long e = 0;
        if (i < total) {
            e = stage[i];
            float v = __uint_as_float((unsigned)(e >> 32));
            unsigned low = (unsigned)e;
            unsigned row = (low >> 10) & 127u;
            if (v <= ordered_to_float(s_min[row]) + EPS_MARGIN) {
                if (s_pcount[row] == 1u && !oflow) {
                    unsigned pix = low >> 10, k = low & 1023u;
                    float full = __fadd_rn(s_A[row], v);   // A + (cn - 2dot)
                    unsigned long long key =
                        ((unsigned long long)float_to_ordered(full) << 32) |
                        (unsigned long long)k;
                    atomicMin(&g_best[pix], key);
                } else {
                    pred = true;
                }
            }
        }
        unsigned mask = __ballot_sync(0xFFFFFFFFu, pred);
        if (mask) {
            int leader = __ffs(mask) - 1;
            unsigned bidx = 0;
            if (lane == leader) bidx = atomicAdd(&g_ncand, (unsigned)__popc(mask));
            bidx = __shfl_sync(0xFFFFFFFFu, bidx, leader);
            if (pred) {
                unsigned dst = bidx + __popc(mask & ((1u << lane) - 1u));
                if (dst < CAND_CAP) g_cand[dst] = e;
            }
        }
    }
}

// ---------------------------------------------------------------------------
// Kernel 4: exact fp32 rescore of multi-candidate entries (one warp each).
// score = fl(fl(A - 2*dot) + cn)  — the Round-2-validated rounding chain.
// ---------------------------------------------------------------------------
__global__ __launch_bounds__(256)
void rescore_kernel(const float* __restrict__ C) {
    const unsigned int count = min(g_ncand, (unsigned)CAND_CAP);
    const int lane = threadIdx.x & 31;
    const unsigned gw = (blockIdx.x * blockDim.x + threadIdx.x) >> 5;
    const unsigned nw = (gridDim.x * blockDim.x) >> 5;

    for (unsigned i = gw; i < count; i += nw) {
        unsigned long long e = g_cand[i];
        unsigned low = (unsigned)e;
        unsigned pix = low >> 10, k = low & 1023u;

        const float4* xr = reinterpret_cast<const float4*>(g_Xt + (size_t)pix * D_);
        const float4* cr = reinterpret_cast<const float4*>(C + (size_t)k * D_);
        float dot = 0.f;
        #pragma unroll
        for (int t = 0; t < 2; t++) {
            float4 xv = xr[lane * 2 + t];
            float4 cv = cr[lane * 2 + t];
            dot = fmaf(xv.x, cv.x, dot);
            dot = fmaf(xv.y, cv.y, dot);
            dot = fmaf(xv.z, cv.z, dot);
            dot = fmaf(xv.w, cv.w, dot);
        }
        #pragma unroll
        for (int o = 16; o > 0; o >>= 1) dot += __shfl_down_sync(0xFFFFFFFFu, dot, o);
        if (lane == 0) {
            float sc = __fadd_rn(__fadd_rn(g_A[pix], __fmul_rn(-2.0f, dot)), g_cn[k]);
            unsigned long long key =
                ((unsigned long long)float_to_ordered(sc) << 32) | (unsigned long long)k;
            atomicMin(&g_best[pix], key);
        }
    }
}

// ---------------------------------------------------------------------------
// Kernel 5: gather output (NCHW), smem-staged code rows (stride-257,
// conflict-free reads) + per-block loss partial from g_best keys.
// ---------------------------------------------------------------------------
__global__ __launch_bounds__(256)
void gather_kernel(const float* __restrict__ C, float* __restrict__ out) {
    __shared__ float rows[32][257];
    __shared__ int s_k[32];
    const int tid = threadIdx.x, lane = tid & 31, wid = tid >> 5;
    const int b  = blockIdx.x >> 5;
    const int pB = (blockIdx.x & 31) * 32;

    if (tid < 32) {
        unsigned long long key = g_best[b * HW_ + pB + tid];
        s_k[tid] = (int)(unsigned int)(key & 1023u);
        float sc = ordered_to_float((unsigned)(key >> 32));
        #pragma unroll
        for (int o = 16; o > 0; o >>= 1) sc += __shfl_down_sync(0xFFFFFFFFu, sc, o);
        if (tid == 0) g_part[blockIdx.x] = sc;
    }
    __syncthreads();

    const float4* C4 = reinterpret_cast<const float4*>(C);
    #pragma unroll
    for (int i = 0; i < 8; i++) {
        int idx = i * 256 + tid;          // 0..2047
        int r = idx >> 6, c = idx & 63;
        float4 v = C4[s_k[r] * 64 + c];
        rows[r][c * 4 + 0] = v.x;
        rows[r][c * 4 + 1] = v.y;
        rows[r][c * 4 + 2] = v.z;
        rows[r][c * 4 + 3] = v.w;
    }
    __syncthreads();

    float* ob = out + (size_t)b * D_ * HW_ + pB;
    #pragma unroll
    for (int it = 0; it < 32; it++) {
        int d = it * 8 + wid;
        ob[(size_t)d * HW_ + lane] = rows[lane][d];
    }
}

// ---------------------------------------------------------------------------
// Kernel 6: loss = 1.25 * sum(g_part) / NELM  (2048 partials, deterministic).
// ---------------------------------------------------------------------------
__global__ __launch_bounds__(1024)
void finalize_kernel(float* __restrict__ out, int loss_idx) {
    __shared__ double red[1024];
    double s = 0.0;
    for (int i = threadIdx.x; i < NPIX / 32; i += 1024)
        s += (double)g_part[i];
    red[threadIdx.x] = s;
    __syncthreads();
    for (int o = 512; o > 0; o >>= 1) {
        if (threadIdx.x < o) red[threadIdx.x] += red[threadIdx.x + o];
        __syncthreads();
    }
    if (threadIdx.x == 0)
        out[loss_idx] = (float)(1.25 * red[0] / (double)NELM);
}

// ---------------------------------------------------------------------------
extern "C" void kernel_launch(void* const* d_in, const int* in_sizes, int n_in,
                              void* d_out, int out_size) {
    const float* X = (const float*)d_in[0];   // [64,256,32,32] f32 NCHW
    const float* C = (const float*)d_in[1];   // [1024,256] f32
    float* out = (float*)d_out;

    static const int SMEM_BYTES = 98304 + 128;   // A(64K) + B(32K) + align slack
    cudaFuncSetAttribute(vq_mma_kernel,
                         cudaFuncAttributeMaxDynamicSharedMemorySize, SMEM_BYTES);

    cn_cbf_kernel<<<K_ / 32, 256>>>(C);
    prep_kernel<<<NPIX / 256, 256>>>(X);
    vq_mma_kernel<<<NPIX / 128, 256, SMEM_BYTES>>>();
    rescore_kernel<<<512, 256>>>(C);
    gather_kernel<<<NPIX / 32, 256>>>(C, out);
    if (out_size > NELM) {
        finalize_kernel<<<1, 1024>>>(out, out_size - 1);
    }
}